// round 2
// baseline (speedup 1.0000x reference)
#include <cuda_runtime.h>
#include <math.h>

#define Bc 8
#define Nc 4096
#define Dc 768
#define Ec 8
#define ESc 16
#define Hc 3072
#define NCHUNK 32
#define TOK 128

typedef unsigned long long u64;
typedef unsigned int u32;

// ----------------- scratch (device globals; allocation is forbidden) -----------------
__device__ float g_logits[Bc * Nc * ESc];                  // [b][n][16]   2 MB
__device__ float g_pxs[Bc * NCHUNK * ESc * Dc];            // [b][c][es][d] 12.6 MB
__device__ u64   g_xs2[Ec * Dc * 8];                       // [e][d][rp]  row-pair packed
__device__ u32   g_cmaxb[Bc * ESc];                        // encoded col max
__device__ float g_cmaxf[Bc * ESc];
__device__ float g_csp[Bc * NCHUNK * ESc];                 // partial exp sums
__device__ float g_inv[Bc * ESc];                          // 1/colsum
__device__ u64   g_h2[Ec * Hc * 8];                        // [e][f][rp]  gelu output, packed
__device__ float g_ys[Bc * ESc * Dc];                      // [b][es][d]

// ----------------- f32x2 helpers -----------------
__device__ __forceinline__ u64 pk2(float x, float y) {
    u64 r; asm("mov.b64 %0, {%1, %2};" : "=l"(r) : "f"(x), "f"(y)); return r;
}
__device__ __forceinline__ u64 dup2(float x) {
    u64 r; asm("mov.b64 %0, {%1, %1};" : "=l"(r) : "f"(x)); return r;
}
__device__ __forceinline__ void up2(u64 v, float& x, float& y) {
    asm("mov.b64 {%0, %1}, %2;" : "=f"(x), "=f"(y) : "l"(v));
}
__device__ __forceinline__ void fma2(u64& d, u64 a, u64 b) {
    asm("fma.rn.f32x2 %0, %1, %2, %0;" : "+l"(d) : "l"(a), "l"(b));
}
__device__ __forceinline__ u64 add2(u64 a, u64 b) {
    u64 r; asm("add.rn.f32x2 %0, %1, %2;" : "=l"(r) : "l"(a), "l"(b)); return r;
}

__device__ __forceinline__ u32 encf(float f) {
    u32 u = __float_as_uint(f);
    return (u & 0x80000000u) ? ~u : (u | 0x80000000u);
}
__device__ __forceinline__ float decf(u32 v) {
    return (v & 0x80000000u) ? __uint_as_float(v ^ 0x80000000u) : __uint_as_float(~v);
}
__device__ __forceinline__ float gelu_exact(float v) {
    return 0.5f * v * (1.0f + erff(v * 0.70710678118654752f));
}

// ================= K0: reset encoded column-max =================
__global__ void k0_init() {
    if (threadIdx.x < Bc * ESc) g_cmaxb[threadIdx.x] = 0u;  // encodes "-infinity"
}

// ================= K1: fused logits + dispatch softmax + partial xs =================
// grid (32, 8), 256 threads, dynamic smem 64KB
extern "C" __global__ void __launch_bounds__(256)
k1_fused(const float* __restrict__ x, const float* __restrict__ phi) {
    extern __shared__ float smemf[];
    float* phiT = smemf;                 // [16][768]  48KB
    float* lsm  = smemf + ESc * Dc;      // [128][16]   8KB
    float* dsm  = smemf + ESc * Dc + TOK * ESc; // [128][16] 8KB

    const int b = blockIdx.y, chunk = blockIdx.x;
    const int tid = threadIdx.x, wid = tid >> 5, lane = tid & 31;
    const float* xb = x + (size_t)b * Nc * Dc;

    // load phi transposed: phi is [d][16]
    for (int i = tid; i < Dc * ESc; i += 256) {
        int d = i >> 4, es = i & 15;
        phiT[es * Dc + d] = phi[i];
    }
    __syncthreads();

    // ---- Phase A: logits, warp handles 16 tokens as 4 quads ----
    const int tokw = chunk * TOK + wid * 16;
    for (int it = 0; it < 4; ++it) {
        const float* xr0 = xb + (size_t)(tokw + it * 4) * Dc;
        u64 v[32];
        #pragma unroll
        for (int i = 0; i < 32; ++i) v[i] = 0ull;
        #pragma unroll
        for (int k = 0; k < 6; ++k) {
            const int d = (lane << 2) + (k << 7);
            float4 x0 = *(const float4*)(xr0 + d);
            float4 x1 = *(const float4*)(xr0 + Dc + d);
            float4 x2 = *(const float4*)(xr0 + 2 * Dc + d);
            float4 x3 = *(const float4*)(xr0 + 3 * Dc + d);
            u64 a0[4], a1[4];
            a0[0] = pk2(x0.x, x1.x); a0[1] = pk2(x0.y, x1.y);
            a0[2] = pk2(x0.z, x1.z); a0[3] = pk2(x0.w, x1.w);
            a1[0] = pk2(x2.x, x3.x); a1[1] = pk2(x2.y, x3.y);
            a1[2] = pk2(x2.z, x3.z); a1[3] = pk2(x2.w, x3.w);
            #pragma unroll
            for (int es = 0; es < 16; ++es) {
                float4 pv = *(const float4*)&phiT[es * Dc + d];
                u64 bd;
                bd = dup2(pv.x); fma2(v[es], a0[0], bd); fma2(v[16 + es], a1[0], bd);
                bd = dup2(pv.y); fma2(v[es], a0[1], bd); fma2(v[16 + es], a1[1], bd);
                bd = dup2(pv.z); fma2(v[es], a0[2], bd); fma2(v[16 + es], a1[2], bd);
                bd = dup2(pv.w); fma2(v[es], a0[3], bd); fma2(v[16 + es], a1[3], bd);
            }
        }
        // split-butterfly reduce: 32 u64 values -> 1 per lane (lane L holds flat index L)
        #pragma unroll
        for (int r = 0; r < 5; ++r) {
            const int bit = 16 >> r;
            const bool upper = (lane & bit) != 0;
            #pragma unroll
            for (int i = 0; i < 16; ++i) {
                if (i < bit) {
                    u64 send = upper ? v[i] : v[i + bit];
                    u64 recv = __shfl_xor_sync(0xffffffffu, send, bit);
                    u64 keep = upper ? v[i + bit] : v[i];
                    v[i] = add2(keep, recv);
                }
            }
        }
        {
            float lo, hi; up2(v[0], lo, hi);
            const int es = lane & 15;
            const int trel = wid * 16 + it * 4 + ((lane >> 4) << 1);
            lsm[trel * ESc + es] = lo;
            lsm[(trel + 1) * ESc + es] = hi;
        }
    }
    __syncthreads();

    // write logits to global (coalesced)
    {
        const size_t lbase = ((size_t)b * Nc + chunk * TOK) * ESc;
        for (int i = tid; i < TOK * ESc; i += 256) g_logits[lbase + i] = lsm[i];
    }

    // ---- Phase B: dispatch softmax (tid<128) + column max (tid 128..143) ----
    if (tid < TOK) {
        float l[16];
        #pragma unroll
        for (int es = 0; es < 16; ++es) l[es] = lsm[tid * ESc + es];
        float m = l[0];
        #pragma unroll
        for (int es = 1; es < 16; ++es) m = fmaxf(m, l[es]);
        float s = 0.f;
        #pragma unroll
        for (int es = 0; es < 16; ++es) { l[es] = __expf(l[es] - m); s += l[es]; }
        // use expf-accurate: recompute with expf for precision
        // (softmax of 16; __expf rel err ~2^-22 is fine, keep)
        float inv = 1.f / s;
        #pragma unroll
        for (int es = 0; es < 16; ++es) dsm[tid * ESc + es] = l[es] * inv;
    } else if (tid < TOK + 16) {
        const int es = tid - TOK;
        float m = lsm[es];
        for (int t = 1; t < TOK; ++t) m = fmaxf(m, lsm[t * ESc + es]);
        atomicMax(&g_cmaxb[b * ESc + es], encf(m));
    }
    __syncthreads();

    // ---- Phase C: partial xs GEMM  [16 es x 128 tok] @ [128 tok x 768 d] ----
    {
        u64 acc[8][3];
        #pragma unroll
        for (int ep = 0; ep < 8; ++ep)
            #pragma unroll
            for (int j = 0; j < 3; ++j) acc[ep][j] = 0ull;

        const float* xc = xb + (size_t)(chunk * TOK) * Dc;
        for (int t = 0; t < TOK; ++t) {
            float xv0 = __ldg(xc + (size_t)t * Dc + tid);
            float xv1 = __ldg(xc + (size_t)t * Dc + tid + 256);
            float xv2 = __ldg(xc + (size_t)t * Dc + tid + 512);
            u64 xd0 = dup2(xv0), xd1 = dup2(xv1), xd2 = dup2(xv2);
            const u64* dp = (const u64*)&dsm[t * ESc];
            #pragma unroll
            for (int ep = 0; ep < 8; ++ep) {
                u64 w = dp[ep];   // (disp[2ep], disp[2ep+1]) broadcast
                fma2(acc[ep][0], xd0, w);
                fma2(acc[ep][1], xd1, w);
                fma2(acc[ep][2], xd2, w);
            }
        }
        float* out = g_pxs + ((size_t)(b * NCHUNK + chunk) * ESc) * Dc;
        #pragma unroll
        for (int ep = 0; ep < 8; ++ep) {
            #pragma unroll
            for (int j = 0; j < 3; ++j) {
                float lo, hi; up2(acc[ep][j], lo, hi);
                out[(2 * ep) * Dc + tid + 256 * j] = lo;
                out[(2 * ep + 1) * Dc + tid + 256 * j] = hi;
            }
        }
    }
}

// ================= K2: reduce xs partials + pack row pairs =================
__global__ void __launch_bounds__(256) k2_reduce_xs() {
    const int idx = blockIdx.x * 256 + threadIdx.x;   // 98304 total
    const int b = idx / (ESc * Dc);
    const int rem = idx % (ESc * Dc);
    const int es = rem / Dc, d = rem % Dc;
    float s = 0.f;
    #pragma unroll 8
    for (int c = 0; c < NCHUNK; ++c)
        s += g_pxs[((size_t)(b * NCHUNK + c)) * (ESc * Dc) + rem];
    const int e = es >> 1, sl = es & 1, row = b * 2 + sl;
    ((float*)g_xs2)[((size_t)e * Dc + d) * 16 + row] = s;
}

// ================= K3: combine partial sums (per chunk) =================
__global__ void __launch_bounds__(256) k3_combine_partial() {
    __shared__ float ps[TOK][ESc];
    __shared__ float cm[ESc];
    const int b = blockIdx.y, chunk = blockIdx.x, tid = threadIdx.x;
    if (tid < 16) cm[tid] = decf(g_cmaxb[b * ESc + tid]);
    __syncthreads();
    if (tid < TOK) {
        const int n = chunk * TOK + tid;
        const float* lp = g_logits + ((size_t)b * Nc + n) * ESc;
        #pragma unroll
        for (int es = 0; es < 16; ++es) ps[tid][es] = expf(lp[es] - cm[es]);
    }
    __syncthreads();
    if (tid < 16) {
        float s = 0.f;
        for (int t = 0; t < TOK; ++t) s += ps[t][tid];
        g_csp[(b * NCHUNK + chunk) * ESc + tid] = s;
    }
}

// ================= K4: finalize colmax/inv-sum =================
__global__ void k4_finalize() {
    const int i = threadIdx.x;  // b*16+es, 128 threads
    if (i >= Bc * ESc) return;
    const int b = i >> 4, es = i & 15;
    float s = 0.f;
    for (int c = 0; c < NCHUNK; ++c) s += g_csp[(b * NCHUNK + c) * ESc + es];
    g_inv[i] = 1.f / s;
    g_cmaxf[i] = decf(g_cmaxb[i]);
}

// ================= K5: FFN1 + GELU  (grid (24, 8)) =================
__global__ void __launch_bounds__(256)
k5_ffn1(const float* __restrict__ w1, const float* __restrict__ b1) {
    __shared__ u64 xsm[Dc * 8];   // 48KB, [d][rp]
    const int e = blockIdx.y;
    const int fbase = blockIdx.x * 128;
    const int tid = threadIdx.x;
    for (int i = tid; i < Dc * 8; i += 256) xsm[i] = g_xs2[(size_t)e * Dc * 8 + i];
    __syncthreads();

    const int f = fbase + (tid & 127);
    const int rg = tid >> 7;           // 0 or 1: rows rg*8 .. rg*8+7
    u64 a0 = 0, a1 = 0, a2 = 0, a3 = 0;
    const float* w = w1 + (size_t)e * Dc * Hc + f;
    #pragma unroll 4
    for (int d = 0; d < Dc; ++d) {
        u64 wd = dup2(__ldg(w + (size_t)d * Hc));
        const u64* xp = &xsm[d * 8 + rg * 4];
        fma2(a0, wd, xp[0]); fma2(a1, wd, xp[1]);
        fma2(a2, wd, xp[2]); fma2(a3, wd, xp[3]);
    }
    const float bv = b1[e * Hc + f];
    u64* hout = g_h2 + ((size_t)e * Hc + f) * 8 + rg * 4;
    u64 accs[4] = {a0, a1, a2, a3};
    #pragma unroll
    for (int i = 0; i < 4; ++i) {
        float lo, hi; up2(accs[i], lo, hi);
        hout[i] = pk2(gelu_exact(lo + bv), gelu_exact(hi + bv));
    }
}

// ================= K6: FFN2 + bias  (grid (12, 8)) =================
__global__ void __launch_bounds__(256)
k6_ffn2(const float* __restrict__ w2, const float* __restrict__ b2) {
    __shared__ float red[4][64][16];  // 16KB
    const int e = blockIdx.y;
    const int d0 = blockIdx.x * 64;
    const int tid = threadIdx.x;
    const int di = tid & 63, fs = tid >> 6;
    const int d = d0 + di;

    u64 acc[8];
    #pragma unroll
    for (int i = 0; i < 8; ++i) acc[i] = 0ull;
    const float* w = w2 + (size_t)e * Hc * Dc + d;
    const u64* h = g_h2 + (size_t)e * Hc * 8;
    const int f0 = fs * 768;
    #pragma unroll 2
    for (int f = f0; f < f0 + 768; ++f) {
        u64 wd = dup2(__ldg(w + (size_t)f * Dc));
        const u64* hp = h + f * 8;
        #pragma unroll
        for (int rp = 0; rp < 8; ++rp) fma2(acc[rp], wd, hp[rp]);
    }
    #pragma unroll
    for (int rp = 0; rp < 8; ++rp) {
        float lo, hi; up2(acc[rp], lo, hi);
        red[fs][di][2 * rp] = lo;
        red[fs][di][2 * rp + 1] = hi;
    }
    __syncthreads();
    #pragma unroll
    for (int q = 0; q < 4; ++q) {
        const int idx = tid * 4 + q;          // 1024 outputs
        const int r = idx & 15, dd = idx >> 4;
        float v = red[0][dd][r] + red[1][dd][r] + red[2][dd][r] + red[3][dd][r]
                + b2[e * Dc + d0 + dd];
        const int bb = r >> 1, ss = r & 1, es = e * 2 + ss;
        g_ys[((size_t)bb * ESc + es) * Dc + d0 + dd] = v;
    }
}

// ================= K7: combine softmax + y = c @ ys  (grid (32, 8)) =================
extern "C" __global__ void __launch_bounds__(256)
k7_combine(float* __restrict__ y) {
    extern __shared__ float smemf[];
    float* ysm = smemf;                       // [16][768]
    float* csm = smemf + ESc * Dc;            // [16][128]
    float* cm  = smemf + ESc * Dc + ESc * TOK;    // [16]
    float* inv = cm + 16;                     // [16]

    const int b = blockIdx.y, chunk = blockIdx.x, tid = threadIdx.x;
    for (int i = tid; i < ESc * Dc; i += 256) ysm[i] = g_ys[(size_t)b * ESc * Dc + i];
    if (tid < 16) { cm[tid] = g_cmaxf[b * ESc + tid]; inv[tid] = g_inv[b * ESc + tid]; }
    __syncthreads();

    if (tid < TOK) {
        const int n = chunk * TOK + tid;
        const float* lp = g_logits + ((size_t)b * Nc + n) * ESc;
        #pragma unroll
        for (int es = 0; es < 16; ++es)
            csm[es * TOK + tid] = expf(lp[es] - cm[es]) * inv[es];
    }
    __syncthreads();

    const int dg = tid & 63, tg = tid >> 6;
    const int dbase = dg * 4;
    float* yb = y + ((size_t)b * Nc + chunk * TOK) * Dc;
    for (int tq = 0; tq < 8; ++tq) {
        const int trel = tg * 32 + tq * 4;
        u64 acc[4][3][2];
        #pragma unroll
        for (int t = 0; t < 4; ++t)
            #pragma unroll
            for (int j = 0; j < 3; ++j) { acc[t][j][0] = 0ull; acc[t][j][1] = 0ull; }
        #pragma unroll
        for (int es = 0; es < 16; ++es) {
            float4 c4 = *(const float4*)&csm[es * TOK + trel];
            u64 cd0 = dup2(c4.x), cd1 = dup2(c4.y), cd2 = dup2(c4.z), cd3 = dup2(c4.w);
            #pragma unroll
            for (int j = 0; j < 3; ++j) {
                float4 yv = *(const float4*)&ysm[es * Dc + dbase + 256 * j];
                u64 ylo = pk2(yv.x, yv.y), yhi = pk2(yv.z, yv.w);
                fma2(acc[0][j][0], cd0, ylo); fma2(acc[0][j][1], cd0, yhi);
                fma2(acc[1][j][0], cd1, ylo); fma2(acc[1][j][1], cd1, yhi);
                fma2(acc[2][j][0], cd2, ylo); fma2(acc[2][j][1], cd2, yhi);
                fma2(acc[3][j][0], cd3, ylo); fma2(acc[3][j][1], cd3, yhi);
            }
        }
        #pragma unroll
        for (int t = 0; t < 4; ++t) {
            float* yr = yb + (size_t)(trel + t) * Dc;
            #pragma unroll
            for (int j = 0; j < 3; ++j) {
                float4 o;
                up2(acc[t][j][0], o.x, o.y);
                up2(acc[t][j][1], o.z, o.w);
                *(float4*)(yr + dbase + 256 * j) = o;
            }
        }
    }
}

// ================= host =================
extern "C" void kernel_launch(void* const* d_in, const int* in_sizes, int n_in,
                              void* d_out, int out_size) {
    const float* x   = (const float*)d_in[0];
    const float* phi = (const float*)d_in[1];
    const float* w1  = (const float*)d_in[2];
    const float* b1  = (const float*)d_in[3];
    const float* w2  = (const float*)d_in[4];
    const float* b2  = (const float*)d_in[5];
    float* y = (float*)d_out;

    static bool attr_done = false;
    // setting attributes is idempotent and not a captured stream op
    cudaFuncSetAttribute(k1_fused, cudaFuncAttributeMaxDynamicSharedMemorySize,
                         (ESc * Dc + 2 * TOK * ESc) * sizeof(float));
    cudaFuncSetAttribute(k7_combine, cudaFuncAttributeMaxDynamicSharedMemorySize,
                         (ESc * Dc + ESc * TOK + 32) * sizeof(float));
    (void)attr_done; (void)in_sizes; (void)n_in; (void)out_size;

    k0_init<<<1, 128>>>();
    k1_fused<<<dim3(NCHUNK, Bc), 256, (ESc * Dc + 2 * TOK * ESc) * sizeof(float)>>>(x, phi);
    k2_reduce_xs<<<(Bc * ESc * Dc) / 256, 256>>>();
    k3_combine_partial<<<dim3(NCHUNK, Bc), 256>>>();
    k4_finalize<<<1, 128>>>();
    k5_ffn1<<<dim3(Hc / 128, Ec), 256>>>(w1, b1);
    k6_ffn2<<<dim3(Dc / 64, Ec), 256>>>(w2, b2);
    k7_combine<<<dim3(NCHUNK, Bc), 256, (ESc * Dc + ESc * TOK + 32) * sizeof(float)>>>(y);
}

// round 3
// speedup vs baseline: 1.6957x; 1.6957x over previous
#include <cuda_runtime.h>
#include <math.h>

#define Bc 8
#define Nc 4096
#define Dc 768
#define Ec 8
#define ESc 16
#define Hc 3072
#define NCHUNK 32
#define TOK 128

typedef unsigned long long u64;
typedef unsigned int u32;

// ----------------- scratch (device globals; allocation is forbidden) -----------------
__device__ float g_logits[Bc * Nc * ESc];                       // [b][n][16]   2 MB
__device__ float g_pxs[Bc * NCHUNK * ESc * Dc];                 // [b][c][es][d]
__device__ __align__(16) u64 g_xs2[Ec * Dc * 8];                // [e][d][rp]
__device__ float g_mch[Bc * NCHUNK * ESc];                      // per-chunk col max
__device__ float g_sch[Bc * NCHUNK * ESc];                      // per-chunk exp-sum (vs chunk max)
__device__ float g_cmaxf[Bc * ESc];
__device__ float g_inv[Bc * ESc];
__device__ __align__(16) u64 g_h2[Ec * Hc * 8];                 // [e][f][rp]
__device__ float g_ys[Bc * ESc * Dc];                           // [b][es][d]

// ----------------- f32x2 helpers -----------------
__device__ __forceinline__ u64 pk2(float x, float y) {
    u64 r; asm("mov.b64 %0, {%1, %2};" : "=l"(r) : "f"(x), "f"(y)); return r;
}
__device__ __forceinline__ u64 dup2(float x) {
    u64 r; asm("mov.b64 %0, {%1, %1};" : "=l"(r) : "f"(x)); return r;
}
__device__ __forceinline__ void up2(u64 v, float& x, float& y) {
    asm("mov.b64 {%0, %1}, %2;" : "=f"(x), "=f"(y) : "l"(v));
}
__device__ __forceinline__ void fma2(u64& d, u64 a, u64 b) {
    asm("fma.rn.f32x2 %0, %1, %2, %0;" : "+l"(d) : "l"(a), "l"(b));
}
__device__ __forceinline__ float gelu_exact(float v) {
    return 0.5f * v * (1.0f + erff(v * 0.70710678118654752f));
}

// smem float offsets for k1
#define OFF_XT   0                       // 64 x 129
#define OFF_PHI  8256                    // 6144 u64 = 12288 floats
#define OFF_PLSM 20544                   // 128 x 16
#define OFF_LSM  22592                   // 128 x 16
#define OFF_DSM  24640                   // 128 x 16
#define OFF_GM   26688                   // 16 x 16
#define OFF_PS   26944                   // 16 x 16
#define OFF_CM   27200                   // 16
#define K1_SMEM_FLOATS 27216

// ================= K1: fused logits + dispatch softmax + chunk colstats + partial xs ===
// grid (32, 8), 256 threads
extern "C" __global__ void __launch_bounds__(256)
k1_fused(const float* __restrict__ x, const float* __restrict__ phi) {
    extern __shared__ float smemf[];
    float* xT   = smemf + OFF_XT;
    u64*   phiD = (u64*)(smemf + OFF_PHI);
    float* plsm = smemf + OFF_PLSM;
    float* lsm  = smemf + OFF_LSM;
    float* dsm  = smemf + OFF_DSM;
    float* gm   = smemf + OFF_GM;
    float* ps   = smemf + OFF_PS;
    float* cm   = smemf + OFF_CM;

    const int b = blockIdx.y, chunk = blockIdx.x;
    const int tid = threadIdx.x;
    const float* xc = x + ((size_t)b * Nc + chunk * TOK) * Dc;

    // phi is [768][16] floats = [768][8] u64 pairs -> straight copy
    {
        const u64* ph = (const u64*)phi;
        for (int i = tid; i < Dc * 8; i += 256) phiD[i] = ph[i];
    }

    // ---- Phase A: logits. thread = (tok, half); half h covers dd in [h*32, h*32+32) ----
    const int tok = tid & 127;
    const int hlf = tid >> 7;
    u64 acc[8];
    #pragma unroll
    for (int j = 0; j < 8; ++j) acc[j] = 0ull;

    for (int db = 0; db < 12; ++db) {
        const int d0 = db * 64;
        __syncthreads();
        // stage x[128 tok][64 d] transposed: xT[dd][tok], stride 129
        #pragma unroll 4
        for (int i = tid; i < TOK * 64; i += 256) {
            const int t = i >> 6, dd = i & 63;
            xT[dd * 129 + t] = xc[(size_t)t * Dc + d0 + dd];
        }
        __syncthreads();
        const ulonglong2* pp = (const ulonglong2*)phiD;
        #pragma unroll 4
        for (int dd2 = 0; dd2 < 32; ++dd2) {
            const int dd = hlf * 32 + dd2;
            const int d = d0 + dd;
            const float xv = xT[dd * 129 + tok];
            const u64 xd = dup2(xv);
            ulonglong2 q0 = pp[d * 4 + 0];
            ulonglong2 q1 = pp[d * 4 + 1];
            ulonglong2 q2 = pp[d * 4 + 2];
            ulonglong2 q3 = pp[d * 4 + 3];
            fma2(acc[0], xd, q0.x); fma2(acc[1], xd, q0.y);
            fma2(acc[2], xd, q1.x); fma2(acc[3], xd, q1.y);
            fma2(acc[4], xd, q2.x); fma2(acc[5], xd, q2.y);
            fma2(acc[6], xd, q3.x); fma2(acc[7], xd, q3.y);
        }
    }
    __syncthreads();
    // half-1 publishes partials
    if (hlf == 1) {
        u64* pl = (u64*)plsm;
        #pragma unroll
        for (int j = 0; j < 8; ++j) pl[tok * 8 + j] = acc[j];
    }
    __syncthreads();
    // half-0 combines, does dispatch softmax, stores raw logits to lsm
    if (hlf == 0) {
        float l[16];
        const u64* pl = (const u64*)plsm;
        #pragma unroll
        for (int j = 0; j < 8; ++j) {
            float a0, a1, b0, b1;
            up2(acc[j], a0, a1);
            up2(pl[tok * 8 + j], b0, b1);
            l[2 * j] = a0 + b0;
            l[2 * j + 1] = a1 + b1;
        }
        float m = l[0];
        #pragma unroll
        for (int es = 1; es < 16; ++es) m = fmaxf(m, l[es]);
        float s = 0.f;
        float p[16];
        #pragma unroll
        for (int es = 0; es < 16; ++es) { p[es] = __expf(l[es] - m); s += p[es]; }
        const float inv = 1.f / s;
        u64* dl = (u64*)dsm;
        u64* ll = (u64*)lsm;
        #pragma unroll
        for (int j = 0; j < 8; ++j) {
            dl[tok * 8 + j] = pk2(p[2 * j] * inv, p[2 * j + 1] * inv);
            ll[tok * 8 + j] = pk2(l[2 * j], l[2 * j + 1]);
        }
    }
    __syncthreads();

    // write raw logits to global (coalesced)
    {
        const size_t lbase = ((size_t)b * Nc + chunk * TOK) * ESc;
        #pragma unroll 2
        for (int i = tid; i < TOK * ESc; i += 256) g_logits[lbase + i] = lsm[i];
    }

    // ---- Phase B: per-chunk column stats (16 groups x 16 es) ----
    {
        const int g = tid >> 4, es = tid & 15;
        float m = -1e30f;
        #pragma unroll
        for (int t8 = 0; t8 < 8; ++t8) m = fmaxf(m, lsm[(g * 8 + t8) * ESc + es]);
        gm[g * 16 + es] = m;
    }
    __syncthreads();
    if (tid < 16) {
        float m = gm[tid];
        #pragma unroll
        for (int g = 1; g < 16; ++g) m = fmaxf(m, gm[g * 16 + tid]);
        cm[tid] = m;
    }
    __syncthreads();
    {
        const int g = tid >> 4, es = tid & 15;
        const float m = cm[es];
        float p = 0.f;
        #pragma unroll
        for (int t8 = 0; t8 < 8; ++t8) p += expf(lsm[(g * 8 + t8) * ESc + es] - m);
        ps[g * 16 + es] = p;
    }
    __syncthreads();
    if (tid < 16) {
        float s = 0.f;
        #pragma unroll
        for (int g = 0; g < 16; ++g) s += ps[g * 16 + tid];
        g_mch[((size_t)b * NCHUNK + chunk) * ESc + tid] = cm[tid];
        g_sch[((size_t)b * NCHUNK + chunk) * ESc + tid] = s;
    }

    // ---- Phase C: partial xs GEMM  [16 es x 128 tok] @ [128 tok x 768 d] ----
    {
        u64 acc2[8][3];
        #pragma unroll
        for (int ep = 0; ep < 8; ++ep)
            #pragma unroll
            for (int j = 0; j < 3; ++j) acc2[ep][j] = 0ull;

        const ulonglong2* dp2 = (const ulonglong2*)dsm;
        #pragma unroll 2
        for (int t = 0; t < TOK; ++t) {
            const float xv0 = __ldg(xc + (size_t)t * Dc + tid);
            const float xv1 = __ldg(xc + (size_t)t * Dc + tid + 256);
            const float xv2 = __ldg(xc + (size_t)t * Dc + tid + 512);
            const u64 xd0 = dup2(xv0), xd1 = dup2(xv1), xd2 = dup2(xv2);
            ulonglong2 w0 = dp2[t * 4 + 0];
            ulonglong2 w1 = dp2[t * 4 + 1];
            ulonglong2 w2v = dp2[t * 4 + 2];
            ulonglong2 w3 = dp2[t * 4 + 3];
            fma2(acc2[0][0], xd0, w0.x); fma2(acc2[0][1], xd1, w0.x); fma2(acc2[0][2], xd2, w0.x);
            fma2(acc2[1][0], xd0, w0.y); fma2(acc2[1][1], xd1, w0.y); fma2(acc2[1][2], xd2, w0.y);
            fma2(acc2[2][0], xd0, w1.x); fma2(acc2[2][1], xd1, w1.x); fma2(acc2[2][2], xd2, w1.x);
            fma2(acc2[3][0], xd0, w1.y); fma2(acc2[3][1], xd1, w1.y); fma2(acc2[3][2], xd2, w1.y);
            fma2(acc2[4][0], xd0, w2v.x); fma2(acc2[4][1], xd1, w2v.x); fma2(acc2[4][2], xd2, w2v.x);
            fma2(acc2[5][0], xd0, w2v.y); fma2(acc2[5][1], xd1, w2v.y); fma2(acc2[5][2], xd2, w2v.y);
            fma2(acc2[6][0], xd0, w3.x); fma2(acc2[6][1], xd1, w3.x); fma2(acc2[6][2], xd2, w3.x);
            fma2(acc2[7][0], xd0, w3.y); fma2(acc2[7][1], xd1, w3.y); fma2(acc2[7][2], xd2, w3.y);
        }
        float* out = g_pxs + ((size_t)(b * NCHUNK + chunk) * ESc) * Dc;
        #pragma unroll
        for (int ep = 0; ep < 8; ++ep) {
            #pragma unroll
            for (int j = 0; j < 3; ++j) {
                float lo, hi; up2(acc2[ep][j], lo, hi);
                out[(2 * ep) * Dc + tid + 256 * j] = lo;
                out[(2 * ep + 1) * Dc + tid + 256 * j] = hi;
            }
        }
    }
}

// ================= K2: reduce xs partials + pack row pairs =================
__global__ void __launch_bounds__(256) k2_reduce_xs() {
    const int idx = blockIdx.x * 256 + threadIdx.x;   // 98304 total
    const int b = idx / (ESc * Dc);
    const int rem = idx % (ESc * Dc);
    const int es = rem / Dc, d = rem % Dc;
    float s = 0.f;
    #pragma unroll 8
    for (int c = 0; c < NCHUNK; ++c)
        s += g_pxs[((size_t)(b * NCHUNK + c)) * (ESc * Dc) + rem];
    const int e = es >> 1, sl = es & 1, row = b * 2 + sl;
    ((float*)g_xs2)[((size_t)e * Dc + d) * 16 + row] = s;
}

// ================= K4: finalize global colmax / inv colsum =================
__global__ void k4_finalize() {
    const int i = threadIdx.x;  // b*16+es
    if (i >= Bc * ESc) return;
    const int b = i >> 4, es = i & 15;
    float M = -1e30f;
    #pragma unroll 8
    for (int c = 0; c < NCHUNK; ++c)
        M = fmaxf(M, g_mch[((size_t)b * NCHUNK + c) * ESc + es]);
    float S = 0.f;
    #pragma unroll 8
    for (int c = 0; c < NCHUNK; ++c) {
        const size_t o = ((size_t)b * NCHUNK + c) * ESc + es;
        S += expf(g_mch[o] - M) * g_sch[o];
    }
    g_cmaxf[i] = M;
    g_inv[i] = 1.f / S;
}

// ================= K5: FFN1 + GELU  (grid (24, 8)) =================
__global__ void __launch_bounds__(256)
k5_ffn1(const float* __restrict__ w1, const float* __restrict__ b1) {
    __shared__ __align__(16) u64 xsm[Dc * 8];   // 48KB, [d][rp]
    const int e = blockIdx.y;
    const int fbase = blockIdx.x * 128;
    const int tid = threadIdx.x;
    for (int i = tid; i < Dc * 8; i += 256) xsm[i] = g_xs2[(size_t)e * Dc * 8 + i];
    __syncthreads();

    const int f = fbase + (tid & 127);
    const int rg = tid >> 7;           // 0 or 1: row-pairs rg*4 .. rg*4+3
    u64 a0 = 0, a1 = 0, a2 = 0, a3 = 0;
    const float* w = w1 + (size_t)e * Dc * Hc + f;
    const ulonglong2* xs2 = (const ulonglong2*)xsm;
    #pragma unroll 4
    for (int d = 0; d < Dc; ++d) {
        const u64 wd = dup2(__ldg(w + (size_t)d * Hc));
        ulonglong2 p0 = xs2[d * 4 + rg * 2];
        ulonglong2 p1 = xs2[d * 4 + rg * 2 + 1];
        fma2(a0, wd, p0.x); fma2(a1, wd, p0.y);
        fma2(a2, wd, p1.x); fma2(a3, wd, p1.y);
    }
    const float bv = b1[e * Hc + f];
    u64* hout = g_h2 + ((size_t)e * Hc + f) * 8 + rg * 4;
    u64 accs[4] = {a0, a1, a2, a3};
    #pragma unroll
    for (int i = 0; i < 4; ++i) {
        float lo, hi; up2(accs[i], lo, hi);
        hout[i] = pk2(gelu_exact(lo + bv), gelu_exact(hi + bv));
    }
}

// ================= K6: FFN2 + bias  (grid (24, 8)) =================
__global__ void __launch_bounds__(256)
k6_ffn2(const float* __restrict__ w2, const float* __restrict__ b2) {
    __shared__ float red[8 * 32 * 17];  // [fs][di][r] padded
    const int e = blockIdx.y;
    const int d0 = blockIdx.x * 32;
    const int tid = threadIdx.x;
    const int di = tid & 31, fs = tid >> 5;

    u64 acc[8];
    #pragma unroll
    for (int i = 0; i < 8; ++i) acc[i] = 0ull;
    const float* w = w2 + (size_t)e * Hc * Dc + d0 + di;
    const ulonglong2* h2 = (const ulonglong2*)(g_h2 + (size_t)e * Hc * 8);
    const int f0 = fs * 384;
    #pragma unroll 2
    for (int f = f0; f < f0 + 384; ++f) {
        const u64 wd = dup2(__ldg(w + (size_t)f * Dc));
        ulonglong2 h0 = h2[f * 4 + 0];
        ulonglong2 h1 = h2[f * 4 + 1];
        ulonglong2 hh2 = h2[f * 4 + 2];
        ulonglong2 h3 = h2[f * 4 + 3];
        fma2(acc[0], wd, h0.x); fma2(acc[1], wd, h0.y);
        fma2(acc[2], wd, h1.x); fma2(acc[3], wd, h1.y);
        fma2(acc[4], wd, hh2.x); fma2(acc[5], wd, hh2.y);
        fma2(acc[6], wd, h3.x); fma2(acc[7], wd, h3.y);
    }
    #pragma unroll
    for (int j = 0; j < 8; ++j) {
        float lo, hi; up2(acc[j], lo, hi);
        red[(fs * 32 + di) * 17 + 2 * j] = lo;
        red[(fs * 32 + di) * 17 + 2 * j + 1] = hi;
    }
    __syncthreads();
    #pragma unroll
    for (int q = 0; q < 2; ++q) {
        const int idx = tid + q * 256;       // 512 outputs
        const int d_loc = idx >> 4, r = idx & 15;
        float v = b2[e * Dc + d0 + d_loc];
        #pragma unroll
        for (int f2 = 0; f2 < 8; ++f2) v += red[(f2 * 32 + d_loc) * 17 + r];
        const int bb = r >> 1, ss = r & 1, es = e * 2 + ss;
        g_ys[((size_t)bb * ESc + es) * Dc + d0 + d_loc] = v;
    }
}

// ================= K7: combine softmax + y = c @ ys  (grid (32, 8)) =================
extern "C" __global__ void __launch_bounds__(256)
k7_combine(float* __restrict__ y) {
    extern __shared__ float smemf[];
    float* ysm = smemf;                       // [16][768]
    float* csm = smemf + ESc * Dc;            // [16][128]
    float* cm  = smemf + ESc * Dc + ESc * TOK;
    float* inv = cm + 16;

    const int b = blockIdx.y, chunk = blockIdx.x, tid = threadIdx.x;
    for (int i = tid; i < ESc * Dc; i += 256) ysm[i] = g_ys[(size_t)b * ESc * Dc + i];
    if (tid < 16) { cm[tid] = g_cmaxf[b * ESc + tid]; inv[tid] = g_inv[b * ESc + tid]; }
    __syncthreads();

    if (tid < TOK) {
        const int n = chunk * TOK + tid;
        const float* lp = g_logits + ((size_t)b * Nc + n) * ESc;
        #pragma unroll
        for (int es = 0; es < 16; ++es)
            csm[es * TOK + tid] = expf(lp[es] - cm[es]) * inv[es];
    }
    __syncthreads();

    const int dg = tid & 63, tg = tid >> 6;
    const int dbase = dg * 4;
    float* yb = y + ((size_t)b * Nc + chunk * TOK) * Dc;
    for (int tq = 0; tq < 8; ++tq) {
        const int trel = tg * 32 + tq * 4;
        u64 acc[4][3][2];
        #pragma unroll
        for (int t = 0; t < 4; ++t)
            #pragma unroll
            for (int j = 0; j < 3; ++j) { acc[t][j][0] = 0ull; acc[t][j][1] = 0ull; }
        #pragma unroll
        for (int es = 0; es < 16; ++es) {
            float4 c4 = *(const float4*)&csm[es * TOK + trel];
            u64 cd0 = dup2(c4.x), cd1 = dup2(c4.y), cd2 = dup2(c4.z), cd3 = dup2(c4.w);
            #pragma unroll
            for (int j = 0; j < 3; ++j) {
                float4 yv = *(const float4*)&ysm[es * Dc + dbase + 256 * j];
                u64 ylo = pk2(yv.x, yv.y), yhi = pk2(yv.z, yv.w);
                fma2(acc[0][j][0], cd0, ylo); fma2(acc[0][j][1], cd0, yhi);
                fma2(acc[1][j][0], cd1, ylo); fma2(acc[1][j][1], cd1, yhi);
                fma2(acc[2][j][0], cd2, ylo); fma2(acc[2][j][1], cd2, yhi);
                fma2(acc[3][j][0], cd3, ylo); fma2(acc[3][j][1], cd3, yhi);
            }
        }
        #pragma unroll
        for (int t = 0; t < 4; ++t) {
            float* yr = yb + (size_t)(trel + t) * Dc;
            #pragma unroll
            for (int j = 0; j < 3; ++j) {
                float4 o;
                up2(acc[t][j][0], o.x, o.y);
                up2(acc[t][j][1], o.z, o.w);
                *(float4*)(yr + dbase + 256 * j) = o;
            }
        }
    }
}

// ================= host =================
extern "C" void kernel_launch(void* const* d_in, const int* in_sizes, int n_in,
                              void* d_out, int out_size) {
    const float* x   = (const float*)d_in[0];
    const float* phi = (const float*)d_in[1];
    const float* w1  = (const float*)d_in[2];
    const float* b1  = (const float*)d_in[3];
    const float* w2  = (const float*)d_in[4];
    const float* b2  = (const float*)d_in[5];
    float* y = (float*)d_out;

    cudaFuncSetAttribute(k1_fused, cudaFuncAttributeMaxDynamicSharedMemorySize,
                         K1_SMEM_FLOATS * sizeof(float));
    cudaFuncSetAttribute(k7_combine, cudaFuncAttributeMaxDynamicSharedMemorySize,
                         (ESc * Dc + ESc * TOK + 32) * sizeof(float));
    (void)in_sizes; (void)n_in; (void)out_size;

    k1_fused<<<dim3(NCHUNK, Bc), 256, K1_SMEM_FLOATS * sizeof(float)>>>(x, phi);
    k2_reduce_xs<<<(Bc * ESc * Dc) / 256, 256>>>();
    k4_finalize<<<1, 128>>>();
    k5_ffn1<<<dim3(Hc / 128, Ec), 256>>>(w1, b1);
    k6_ffn2<<<dim3(Dc / 32, Ec), 256>>>(w2, b2);
    k7_combine<<<dim3(NCHUNK, Bc), 256, (ESc * Dc + ESc * TOK + 32) * sizeof(float)>>>(y);
}

// round 4
// speedup vs baseline: 1.8695x; 1.1025x over previous
#include <cuda_runtime.h>
#include <math.h>

#define Bc 8
#define Nc 4096
#define Dc 768
#define Ec 8
#define ESc 16
#define Hc 3072
#define NCHUNK 32
#define TOK 128

typedef unsigned long long u64;
typedef unsigned int u32;

// ----------------- scratch -----------------
__device__ float g_logits[Bc * Nc * ESc];
__device__ float g_pxs[Bc * NCHUNK * ESc * Dc];
__device__ __align__(16) u64 g_xs2[Ec * Dc * 8];       // [e][d][rp]
__device__ float g_mch[Bc * NCHUNK * ESc];
__device__ float g_sch[Bc * NCHUNK * ESc];
__device__ float g_cmaxf[Bc * ESc];
__device__ float g_inv[Bc * ESc];
__device__ __align__(16) u64 g_h2[Ec * Hc * 8];        // [e][f][rp]
__device__ float g_ys[Bc * ESc * Dc];

// ----------------- f32x2 helpers -----------------
__device__ __forceinline__ u64 pk2(float x, float y) {
    u64 r; asm("mov.b64 %0, {%1, %2};" : "=l"(r) : "f"(x), "f"(y)); return r;
}
__device__ __forceinline__ u64 dup2(float x) {
    u64 r; asm("mov.b64 %0, {%1, %1};" : "=l"(r) : "f"(x)); return r;
}
__device__ __forceinline__ void up2(u64 v, float& x, float& y) {
    asm("mov.b64 {%0, %1}, %2;" : "=f"(x), "=f"(y) : "l"(v));
}
__device__ __forceinline__ void fma2(u64& d, u64 a, u64 b) {
    asm("fma.rn.f32x2 %0, %1, %2, %0;" : "+l"(d) : "l"(a), "l"(b));
}
__device__ __forceinline__ u64 add2(u64 a, u64 b) {
    u64 r; asm("add.rn.f32x2 %0, %1, %2;" : "=l"(r) : "l"(a), "l"(b)); return r;
}
__device__ __forceinline__ float gelu_exact(float v) {
    return 0.5f * v * (1.0f + erff(v * 0.70710678118654752f));
}

// smem float offsets for k1
#define OFF_XT   0                       // 64 x 129
#define OFF_PHI  8256                    // 6144 u64 = 12288 floats
#define OFF_PLSM 20544                   // 128 x 16
#define OFF_LSM  22592                   // 128 x 16
#define OFF_DSM  24640                   // 128 x 16
#define OFF_GM   26688
#define OFF_PS   26944
#define OFF_CM   27200
#define K1_SMEM_FLOATS 27216

// ================= K1: fused logits + dispatch softmax + chunk colstats + partial xs ===
extern "C" __global__ void __launch_bounds__(256)
k1_fused(const float* __restrict__ x, const float* __restrict__ phi) {
    extern __shared__ float smemf[];
    float* xT   = smemf + OFF_XT;
    u64*   phiD = (u64*)(smemf + OFF_PHI);
    float* plsm = smemf + OFF_PLSM;
    float* lsm  = smemf + OFF_LSM;
    float* dsm  = smemf + OFF_DSM;
    float* gm   = smemf + OFF_GM;
    float* ps   = smemf + OFF_PS;
    float* cm   = smemf + OFF_CM;

    const int b = blockIdx.y, chunk = blockIdx.x;
    const int tid = threadIdx.x;
    const float* xc = x + ((size_t)b * Nc + chunk * TOK) * Dc;

    {   // phi [768][16] -> u64 pairs, straight copy
        const u64* ph = (const u64*)phi;
        for (int i = tid; i < Dc * 8; i += 256) phiD[i] = ph[i];
    }

    // ---- Phase A: logits ----
    const int tok = tid & 127;
    const int hlf = tid >> 7;
    u64 acc[8];
    #pragma unroll
    for (int j = 0; j < 8; ++j) acc[j] = 0ull;

    for (int db = 0; db < 12; ++db) {
        const int d0 = db * 64;
        __syncthreads();
        #pragma unroll 4
        for (int i = tid; i < TOK * 64; i += 256) {
            const int t = i >> 6, dd = i & 63;
            xT[dd * 129 + t] = xc[(size_t)t * Dc + d0 + dd];
        }
        __syncthreads();
        const ulonglong2* pp = (const ulonglong2*)phiD;
        #pragma unroll 4
        for (int dd2 = 0; dd2 < 32; ++dd2) {
            const int dd = hlf * 32 + dd2;
            const int d = d0 + dd;
            const float xv = xT[dd * 129 + tok];
            const u64 xd = dup2(xv);
            ulonglong2 q0 = pp[d * 4 + 0];
            ulonglong2 q1 = pp[d * 4 + 1];
            ulonglong2 q2 = pp[d * 4 + 2];
            ulonglong2 q3 = pp[d * 4 + 3];
            fma2(acc[0], xd, q0.x); fma2(acc[1], xd, q0.y);
            fma2(acc[2], xd, q1.x); fma2(acc[3], xd, q1.y);
            fma2(acc[4], xd, q2.x); fma2(acc[5], xd, q2.y);
            fma2(acc[6], xd, q3.x); fma2(acc[7], xd, q3.y);
        }
    }
    __syncthreads();
    if (hlf == 1) {
        u64* pl = (u64*)plsm;
        #pragma unroll
        for (int j = 0; j < 8; ++j) pl[tok * 8 + j] = acc[j];
    }
    __syncthreads();
    if (hlf == 0) {
        float l[16];
        const u64* pl = (const u64*)plsm;
        #pragma unroll
        for (int j = 0; j < 8; ++j) {
            float a0, a1, b0, b1;
            up2(acc[j], a0, a1);
            up2(pl[tok * 8 + j], b0, b1);
            l[2 * j] = a0 + b0;
            l[2 * j + 1] = a1 + b1;
        }
        float m = l[0];
        #pragma unroll
        for (int es = 1; es < 16; ++es) m = fmaxf(m, l[es]);
        float s = 0.f;
        float p[16];
        #pragma unroll
        for (int es = 0; es < 16; ++es) { p[es] = __expf(l[es] - m); s += p[es]; }
        const float inv = 1.f / s;
        u64* dl = (u64*)dsm;
        u64* ll = (u64*)lsm;
        #pragma unroll
        for (int j = 0; j < 8; ++j) {
            dl[tok * 8 + j] = pk2(p[2 * j] * inv, p[2 * j + 1] * inv);
            ll[tok * 8 + j] = pk2(l[2 * j], l[2 * j + 1]);
        }
    }
    __syncthreads();

    {   // raw logits -> global
        const size_t lbase = ((size_t)b * Nc + chunk * TOK) * ESc;
        #pragma unroll 2
        for (int i = tid; i < TOK * ESc; i += 256) g_logits[lbase + i] = lsm[i];
    }

    // ---- Phase B: per-chunk column stats ----
    {
        const int g = tid >> 4, es = tid & 15;
        float m = -1e30f;
        #pragma unroll
        for (int t8 = 0; t8 < 8; ++t8) m = fmaxf(m, lsm[(g * 8 + t8) * ESc + es]);
        gm[g * 16 + es] = m;
    }
    __syncthreads();
    if (tid < 16) {
        float m = gm[tid];
        #pragma unroll
        for (int g = 1; g < 16; ++g) m = fmaxf(m, gm[g * 16 + tid]);
        cm[tid] = m;
    }
    __syncthreads();
    {
        const int g = tid >> 4, es = tid & 15;
        const float m = cm[es];
        float p = 0.f;
        #pragma unroll
        for (int t8 = 0; t8 < 8; ++t8) p += expf(lsm[(g * 8 + t8) * ESc + es] - m);
        ps[g * 16 + es] = p;
    }
    __syncthreads();
    if (tid < 16) {
        float s = 0.f;
        #pragma unroll
        for (int g = 0; g < 16; ++g) s += ps[g * 16 + tid];
        g_mch[((size_t)b * NCHUNK + chunk) * ESc + tid] = cm[tid];
        g_sch[((size_t)b * NCHUNK + chunk) * ESc + tid] = s;
    }

    // ---- Phase C: partial xs, thread = (12 d as 3 float4) x (4 es) ----
    {
        const int f4i = tid & 63;          // d base = f4i*4, plus 256*j
        const int esq = tid >> 6;          // es group: esq*4 .. +3
        u64 acc2[4][3][2];
        #pragma unroll
        for (int e = 0; e < 4; ++e)
            #pragma unroll
            for (int j = 0; j < 3; ++j) { acc2[e][j][0] = 0ull; acc2[e][j][1] = 0ull; }

        const int dbase = f4i * 4;
        #pragma unroll 2
        for (int t = 0; t < TOK; ++t) {
            const float4 xv0 = __ldg((const float4*)(xc + (size_t)t * Dc + dbase));
            const float4 xv1 = __ldg((const float4*)(xc + (size_t)t * Dc + dbase + 256));
            const float4 xv2 = __ldg((const float4*)(xc + (size_t)t * Dc + dbase + 512));
            const u64 x0l = pk2(xv0.x, xv0.y), x0h = pk2(xv0.z, xv0.w);
            const u64 x1l = pk2(xv1.x, xv1.y), x1h = pk2(xv1.z, xv1.w);
            const u64 x2l = pk2(xv2.x, xv2.y), x2h = pk2(xv2.z, xv2.w);
            const float4 dv = *(const float4*)&dsm[t * ESc + esq * 4];
            const u64 w0 = dup2(dv.x), w1 = dup2(dv.y), w2 = dup2(dv.z), w3 = dup2(dv.w);
            fma2(acc2[0][0][0], w0, x0l); fma2(acc2[0][0][1], w0, x0h);
            fma2(acc2[0][1][0], w0, x1l); fma2(acc2[0][1][1], w0, x1h);
            fma2(acc2[0][2][0], w0, x2l); fma2(acc2[0][2][1], w0, x2h);
            fma2(acc2[1][0][0], w1, x0l); fma2(acc2[1][0][1], w1, x0h);
            fma2(acc2[1][1][0], w1, x1l); fma2(acc2[1][1][1], w1, x1h);
            fma2(acc2[1][2][0], w1, x2l); fma2(acc2[1][2][1], w1, x2h);
            fma2(acc2[2][0][0], w2, x0l); fma2(acc2[2][0][1], w2, x0h);
            fma2(acc2[2][1][0], w2, x1l); fma2(acc2[2][1][1], w2, x1h);
            fma2(acc2[2][2][0], w2, x2l); fma2(acc2[2][2][1], w2, x2h);
            fma2(acc2[3][0][0], w3, x0l); fma2(acc2[3][0][1], w3, x0h);
            fma2(acc2[3][1][0], w3, x1l); fma2(acc2[3][1][1], w3, x1h);
            fma2(acc2[3][2][0], w3, x2l); fma2(acc2[3][2][1], w3, x2h);
        }
        float* out = g_pxs + ((size_t)(b * NCHUNK + chunk) * ESc) * Dc;
        #pragma unroll
        for (int e = 0; e < 4; ++e) {
            const int es = esq * 4 + e;
            #pragma unroll
            for (int j = 0; j < 3; ++j) {
                float4 o;
                up2(acc2[e][j][0], o.x, o.y);
                up2(acc2[e][j][1], o.z, o.w);
                *(float4*)(out + (size_t)es * Dc + dbase + 256 * j) = o;
            }
        }
    }
}

// ================= K2: reduce xs partials + pack row pairs =================
__global__ void __launch_bounds__(256) k2_reduce_xs() {
    const int idx = blockIdx.x * 256 + threadIdx.x;
    const int b = idx / (ESc * Dc);
    const int rem = idx % (ESc * Dc);
    const int es = rem / Dc, d = rem % Dc;
    float s = 0.f;
    #pragma unroll 8
    for (int c = 0; c < NCHUNK; ++c)
        s += g_pxs[((size_t)(b * NCHUNK + c)) * (ESc * Dc) + rem];
    const int e = es >> 1, sl = es & 1, row = b * 2 + sl;
    ((float*)g_xs2)[((size_t)e * Dc + d) * 16 + row] = s;
}

// ================= K4: finalize colmax / inv colsum =================
__global__ void k4_finalize() {
    const int i = threadIdx.x;
    if (i >= Bc * ESc) return;
    const int b = i >> 4, es = i & 15;
    float M = -1e30f;
    #pragma unroll 8
    for (int c = 0; c < NCHUNK; ++c)
        M = fmaxf(M, g_mch[((size_t)b * NCHUNK + c) * ESc + es]);
    float S = 0.f;
    #pragma unroll 8
    for (int c = 0; c < NCHUNK; ++c) {
        const size_t o = ((size_t)b * NCHUNK + c) * ESc + es;
        S += expf(g_mch[o] - M) * g_sch[o];
    }
    g_cmaxf[i] = M;
    g_inv[i] = 1.f / S;
}

// ================= K5: FFN1 + GELU  (grid (48, 8)) =================
// thread: fi = t&15 (4 f each), rg = (t>>4)&7 (row-pair), ds = t>>7 (d half)
__global__ void __launch_bounds__(256)
k5_ffn1(const float* __restrict__ w1, const float* __restrict__ b1) {
    __shared__ __align__(16) u64 xsm[Dc * 8];      // 48KB
    __shared__ __align__(16) u64 red[128 * 4];     // 4KB
    const int e = blockIdx.y;
    const int fbase = blockIdx.x * 64;
    const int tid = threadIdx.x;
    for (int i = tid; i < Dc * 8; i += 256) xsm[i] = g_xs2[(size_t)e * Dc * 8 + i];
    __syncthreads();

    const int fi = tid & 15;
    const int rg = (tid >> 4) & 7;
    const int ds = tid >> 7;
    const int f = fbase + fi * 4;

    u64 a0 = 0, a1 = 0, a2 = 0, a3 = 0;
    const float* w = w1 + (size_t)e * Dc * Hc + f;
    const int dlo = ds * 384;
    #pragma unroll 4
    for (int d = dlo; d < dlo + 384; ++d) {
        const float4 wv = __ldg((const float4*)(w + (size_t)d * Hc));
        const u64 xs = xsm[d * 8 + rg];
        fma2(a0, dup2(wv.x), xs);
        fma2(a1, dup2(wv.y), xs);
        fma2(a2, dup2(wv.z), xs);
        fma2(a3, dup2(wv.w), xs);
    }
    const int ri = tid & 127;
    if (ds == 1) {
        red[ri * 4 + 0] = a0; red[ri * 4 + 1] = a1;
        red[ri * 4 + 2] = a2; red[ri * 4 + 3] = a3;
    }
    __syncthreads();
    if (ds == 0) {
        a0 = add2(a0, red[ri * 4 + 0]);
        a1 = add2(a1, red[ri * 4 + 1]);
        a2 = add2(a2, red[ri * 4 + 2]);
        a3 = add2(a3, red[ri * 4 + 3]);
        const float4 bv = __ldg((const float4*)(b1 + (size_t)e * Hc + f));
        u64 accs[4] = {a0, a1, a2, a3};
        const float bvs[4] = {bv.x, bv.y, bv.z, bv.w};
        #pragma unroll
        for (int j = 0; j < 4; ++j) {
            float lo, hi; up2(accs[j], lo, hi);
            g_h2[((size_t)e * Hc + f + j) * 8 + rg] =
                pk2(gelu_exact(lo + bvs[j]), gelu_exact(hi + bvs[j]));
        }
    }
}

// ================= K6: FFN2 + bias  (grid (24, 8)) =================
// thread: dq = t&7 (4 d each), rh = (t>>3)&1 (4 row-pairs), fs = t>>4 (16 f-slices)
__global__ void __launch_bounds__(256)
k6_ffn2(const float* __restrict__ w2, const float* __restrict__ b2) {
    __shared__ __align__(16) u64 red[16 * 256];    // 32KB: [fs][d_loc*8 + rp]
    const int e = blockIdx.y;
    const int d0 = blockIdx.x * 32;
    const int tid = threadIdx.x;
    const int dq = tid & 7, rh = (tid >> 3) & 1, fs = tid >> 4;

    u64 acc[4][4];
    #pragma unroll
    for (int j = 0; j < 4; ++j)
        #pragma unroll
        for (int r = 0; r < 4; ++r) acc[j][r] = 0ull;

    const float* w = w2 + (size_t)e * Hc * Dc + d0 + dq * 4;
    const ulonglong2* h2 = (const ulonglong2*)(g_h2 + (size_t)e * Hc * 8);
    const int f0 = fs * 192;
    #pragma unroll 2
    for (int f = f0; f < f0 + 192; ++f) {
        const float4 wv = __ldg((const float4*)(w + (size_t)f * Dc));
        const ulonglong2 ha = h2[f * 4 + rh * 2];
        const ulonglong2 hb = h2[f * 4 + rh * 2 + 1];
        const u64 wd0 = dup2(wv.x), wd1 = dup2(wv.y), wd2 = dup2(wv.z), wd3 = dup2(wv.w);
        fma2(acc[0][0], wd0, ha.x); fma2(acc[0][1], wd0, ha.y);
        fma2(acc[0][2], wd0, hb.x); fma2(acc[0][3], wd0, hb.y);
        fma2(acc[1][0], wd1, ha.x); fma2(acc[1][1], wd1, ha.y);
        fma2(acc[1][2], wd1, hb.x); fma2(acc[1][3], wd1, hb.y);
        fma2(acc[2][0], wd2, ha.x); fma2(acc[2][1], wd2, ha.y);
        fma2(acc[2][2], wd2, hb.x); fma2(acc[2][3], wd2, hb.y);
        fma2(acc[3][0], wd3, ha.x); fma2(acc[3][1], wd3, ha.y);
        fma2(acc[3][2], wd3, hb.x); fma2(acc[3][3], wd3, hb.y);
    }
    // publish partials: red[fs][ (dq*4+j)*8 + rh*4 + r ]
    #pragma unroll
    for (int j = 0; j < 4; ++j)
        #pragma unroll
        for (int r = 0; r < 4; ++r)
            red[fs * 256 + (dq * 4 + j) * 8 + rh * 4 + r] = acc[j][r];
    __syncthreads();
    // reduce over 16 fs: thread owns (d_loc = t>>3, rp = t&7)
    {
        const int d_loc = tid >> 3, rp = tid & 7;
        u64 s = red[d_loc * 8 + rp];
        #pragma unroll
        for (int f2 = 1; f2 < 16; ++f2) s = add2(s, red[f2 * 256 + d_loc * 8 + rp]);
        float lo, hi; up2(s, lo, hi);
        const float bb2 = __ldg(b2 + (size_t)e * Dc + d0 + d_loc);
        const int r0 = 2 * rp, r1 = 2 * rp + 1;
        const int b_0 = r0 >> 1, s_0 = r0 & 1;
        const int b_1 = r1 >> 1, s_1 = r1 & 1;
        g_ys[((size_t)b_0 * ESc + e * 2 + s_0) * Dc + d0 + d_loc] = lo + bb2;
        g_ys[((size_t)b_1 * ESc + e * 2 + s_1) * Dc + d0 + d_loc] = hi + bb2;
    }
}

// ================= K7: combine softmax + y = c @ ys  (grid (32, 8)) =================
extern "C" __global__ void __launch_bounds__(256)
k7_combine(float* __restrict__ y) {
    extern __shared__ float smemf[];
    float* ysm = smemf;                       // [16][768]
    float* csm = smemf + ESc * Dc;            // [16][128]
    float* cm  = smemf + ESc * Dc + ESc * TOK;
    float* inv = cm + 16;

    const int b = blockIdx.y, chunk = blockIdx.x, tid = threadIdx.x;
    for (int i = tid; i < ESc * Dc; i += 256) ysm[i] = g_ys[(size_t)b * ESc * Dc + i];
    if (tid < 16) { cm[tid] = g_cmaxf[b * ESc + tid]; inv[tid] = g_inv[b * ESc + tid]; }
    __syncthreads();

    if (tid < TOK) {
        const int n = chunk * TOK + tid;
        const float* lp = g_logits + ((size_t)b * Nc + n) * ESc;
        #pragma unroll
        for (int es = 0; es < 16; ++es)
            csm[es * TOK + tid] = expf(lp[es] - cm[es]) * inv[es];
    }
    __syncthreads();

    const int dg = tid & 63, tg = tid >> 6;
    const int dbase = dg * 4;
    float* yb = y + ((size_t)b * Nc + chunk * TOK) * Dc;
    for (int tq = 0; tq < 8; ++tq) {
        const int trel = tg * 32 + tq * 4;
        u64 acc[4][3][2];
        #pragma unroll
        for (int t = 0; t < 4; ++t)
            #pragma unroll
            for (int j = 0; j < 3; ++j) { acc[t][j][0] = 0ull; acc[t][j][1] = 0ull; }
        #pragma unroll
        for (int es = 0; es < 16; ++es) {
            float4 c4 = *(const float4*)&csm[es * TOK + trel];
            u64 cd0 = dup2(c4.x), cd1 = dup2(c4.y), cd2 = dup2(c4.z), cd3 = dup2(c4.w);
            #pragma unroll
            for (int j = 0; j < 3; ++j) {
                float4 yv = *(const float4*)&ysm[es * Dc + dbase + 256 * j];
                u64 ylo = pk2(yv.x, yv.y), yhi = pk2(yv.z, yv.w);
                fma2(acc[0][j][0], cd0, ylo); fma2(acc[0][j][1], cd0, yhi);
                fma2(acc[1][j][0], cd1, ylo); fma2(acc[1][j][1], cd1, yhi);
                fma2(acc[2][j][0], cd2, ylo); fma2(acc[2][j][1], cd2, yhi);
                fma2(acc[3][j][0], cd3, ylo); fma2(acc[3][j][1], cd3, yhi);
            }
        }
        #pragma unroll
        for (int t = 0; t < 4; ++t) {
            float* yr = yb + (size_t)(trel + t) * Dc;
            #pragma unroll
            for (int j = 0; j < 3; ++j) {
                float4 o;
                up2(acc[t][j][0], o.x, o.y);
                up2(acc[t][j][1], o.z, o.w);
                *(float4*)(yr + dbase + 256 * j) = o;
            }
        }
    }
}

// ================= host =================
extern "C" void kernel_launch(void* const* d_in, const int* in_sizes, int n_in,
                              void* d_out, int out_size) {
    const float* x   = (const float*)d_in[0];
    const float* phi = (const float*)d_in[1];
    const float* w1  = (const float*)d_in[2];
    const float* b1  = (const float*)d_in[3];
    const float* w2  = (const float*)d_in[4];
    const float* b2  = (const float*)d_in[5];
    float* y = (float*)d_out;

    cudaFuncSetAttribute(k1_fused, cudaFuncAttributeMaxDynamicSharedMemorySize,
                         K1_SMEM_FLOATS * sizeof(float));
    cudaFuncSetAttribute(k7_combine, cudaFuncAttributeMaxDynamicSharedMemorySize,
                         (ESc * Dc + ESc * TOK + 32) * sizeof(float));
    (void)in_sizes; (void)n_in; (void)out_size;

    k1_fused<<<dim3(NCHUNK, Bc), 256, K1_SMEM_FLOATS * sizeof(float)>>>(x, phi);
    k2_reduce_xs<<<(Bc * ESc * Dc) / 256, 256>>>();
    k4_finalize<<<1, 128>>>();
    k5_ffn1<<<dim3(Hc / 64, Ec), 256>>>(w1, b1);
    k6_ffn2<<<dim3(Dc / 32, Ec), 256>>>(w2, b2);
    k7_combine<<<dim3(NCHUNK, Bc), 256, (ESc * Dc + ESc * TOK + 32) * sizeof(float)>>>(y);
}

// round 5
// speedup vs baseline: 2.7610x; 1.4768x over previous
#include <cuda_runtime.h>
#include <math.h>

#define Bc 8
#define Nc 4096
#define Dc 768
#define Ec 8
#define ESc 16
#define Hc 3072
#define NCHUNK 32
#define TOK 128
#define TOK7 64

typedef unsigned long long u64;
typedef unsigned int u32;

// ----------------- scratch -----------------
__device__ float g_logits[Bc * Nc * ESc];
__device__ float g_pxs[Bc * NCHUNK * ESc * Dc];
__device__ __align__(16) u64 g_xs2[Ec * Dc * 8];       // [e][d][rp]
__device__ float g_mch[Bc * NCHUNK * ESc];
__device__ float g_sch[Bc * NCHUNK * ESc];
__device__ float g_cmaxf[Bc * ESc];
__device__ float g_inv[Bc * ESc];
__device__ __align__(16) u64 g_h2[Ec * Hc * 8];        // [e][f][rp]
__device__ float g_ys[Bc * ESc * Dc];

// ----------------- f32x2 helpers -----------------
__device__ __forceinline__ u64 pk2(float x, float y) {
    u64 r; asm("mov.b64 %0, {%1, %2};" : "=l"(r) : "f"(x), "f"(y)); return r;
}
__device__ __forceinline__ u64 dup2(float x) {
    u64 r; asm("mov.b64 %0, {%1, %1};" : "=l"(r) : "f"(x)); return r;
}
__device__ __forceinline__ void up2(u64 v, float& x, float& y) {
    asm("mov.b64 {%0, %1}, %2;" : "=f"(x), "=f"(y) : "l"(v));
}
__device__ __forceinline__ void fma2(u64& d, u64 a, u64 b) {
    asm("fma.rn.f32x2 %0, %1, %2, %0;" : "+l"(d) : "l"(a), "l"(b));
}
__device__ __forceinline__ u64 add2(u64 a, u64 b) {
    u64 r; asm("add.rn.f32x2 %0, %1, %2;" : "=l"(r) : "l"(a), "l"(b)); return r;
}
__device__ __forceinline__ float gelu_exact(float v) {
    return 0.5f * v * (1.0f + erff(v * 0.70710678118654752f));
}

// smem float offsets for k1
#define OFF_XT   0                       // 64 x 129
#define OFF_PHI  8256                    // 6144 u64 = 12288 floats
#define OFF_PLSM 20544                   // 128 x 16
#define OFF_LSM  22592                   // 128 x 16
#define OFF_DSM  24640                   // 128 x 16
#define OFF_GM   26688
#define OFF_PS   26944
#define OFF_CM   27200
#define K1_SMEM_FLOATS 27216

// ================= K1: fused logits + dispatch softmax + chunk colstats + partial xs ===
extern "C" __global__ void __launch_bounds__(256)
k1_fused(const float* __restrict__ x, const float* __restrict__ phi) {
    extern __shared__ float smemf[];
    float* xT   = smemf + OFF_XT;
    u64*   phiD = (u64*)(smemf + OFF_PHI);
    float* plsm = smemf + OFF_PLSM;
    float* lsm  = smemf + OFF_LSM;
    float* dsm  = smemf + OFF_DSM;
    float* gm   = smemf + OFF_GM;
    float* ps   = smemf + OFF_PS;
    float* cm   = smemf + OFF_CM;

    const int b = blockIdx.y, chunk = blockIdx.x;
    const int tid = threadIdx.x;
    const float* xc = x + ((size_t)b * Nc + chunk * TOK) * Dc;

    {   // phi [768][16] -> u64 pairs, straight copy
        const u64* ph = (const u64*)phi;
        for (int i = tid; i < Dc * 8; i += 256) phiD[i] = ph[i];
    }

    // ---- Phase A: logits ----
    const int tok = tid & 127;
    const int hlf = tid >> 7;
    u64 acc[8];
    #pragma unroll
    for (int j = 0; j < 8; ++j) acc[j] = 0ull;

    for (int db = 0; db < 12; ++db) {
        const int d0 = db * 64;
        __syncthreads();
        // stage x[128 tok][64 d] transposed via float4 loads
        #pragma unroll
        for (int k = 0; k < 8; ++k) {
            const int idx = tid + k * 256;          // 0..2047
            const int t = idx >> 4, dd4 = idx & 15;
            const float4 v = __ldg((const float4*)(xc + (size_t)t * Dc + d0 + dd4 * 4));
            xT[(dd4 * 4 + 0) * 129 + t] = v.x;
            xT[(dd4 * 4 + 1) * 129 + t] = v.y;
            xT[(dd4 * 4 + 2) * 129 + t] = v.z;
            xT[(dd4 * 4 + 3) * 129 + t] = v.w;
        }
        __syncthreads();
        const ulonglong2* pp = (const ulonglong2*)phiD;
        #pragma unroll 4
        for (int dd2 = 0; dd2 < 32; ++dd2) {
            const int dd = hlf * 32 + dd2;
            const int d = d0 + dd;
            const float xv = xT[dd * 129 + tok];
            const u64 xd = dup2(xv);
            ulonglong2 q0 = pp[d * 4 + 0];
            ulonglong2 q1 = pp[d * 4 + 1];
            ulonglong2 q2 = pp[d * 4 + 2];
            ulonglong2 q3 = pp[d * 4 + 3];
            fma2(acc[0], xd, q0.x); fma2(acc[1], xd, q0.y);
            fma2(acc[2], xd, q1.x); fma2(acc[3], xd, q1.y);
            fma2(acc[4], xd, q2.x); fma2(acc[5], xd, q2.y);
            fma2(acc[6], xd, q3.x); fma2(acc[7], xd, q3.y);
        }
    }
    __syncthreads();
    if (hlf == 1) {
        u64* pl = (u64*)plsm;
        #pragma unroll
        for (int j = 0; j < 8; ++j) pl[tok * 8 + j] = acc[j];
    }
    __syncthreads();
    if (hlf == 0) {
        float l[16];
        const u64* pl = (const u64*)plsm;
        #pragma unroll
        for (int j = 0; j < 8; ++j) {
            float a0, a1, b0, b1;
            up2(acc[j], a0, a1);
            up2(pl[tok * 8 + j], b0, b1);
            l[2 * j] = a0 + b0;
            l[2 * j + 1] = a1 + b1;
        }
        float m = l[0];
        #pragma unroll
        for (int es = 1; es < 16; ++es) m = fmaxf(m, l[es]);
        float s = 0.f;
        float p[16];
        #pragma unroll
        for (int es = 0; es < 16; ++es) { p[es] = __expf(l[es] - m); s += p[es]; }
        const float inv = 1.f / s;
        u64* dl = (u64*)dsm;
        u64* ll = (u64*)lsm;
        #pragma unroll
        for (int j = 0; j < 8; ++j) {
            dl[tok * 8 + j] = pk2(p[2 * j] * inv, p[2 * j + 1] * inv);
            ll[tok * 8 + j] = pk2(l[2 * j], l[2 * j + 1]);
        }
    }
    __syncthreads();

    {   // raw logits -> global
        const size_t lbase = ((size_t)b * Nc + chunk * TOK) * ESc;
        #pragma unroll 2
        for (int i = tid; i < TOK * ESc; i += 256) g_logits[lbase + i] = lsm[i];
    }

    // ---- Phase B: per-chunk column stats ----
    {
        const int g = tid >> 4, es = tid & 15;
        float m = -1e30f;
        #pragma unroll
        for (int t8 = 0; t8 < 8; ++t8) m = fmaxf(m, lsm[(g * 8 + t8) * ESc + es]);
        gm[g * 16 + es] = m;
    }
    __syncthreads();
    if (tid < 16) {
        float m = gm[tid];
        #pragma unroll
        for (int g = 1; g < 16; ++g) m = fmaxf(m, gm[g * 16 + tid]);
        cm[tid] = m;
    }
    __syncthreads();
    {
        const int g = tid >> 4, es = tid & 15;
        const float m = cm[es];
        float p = 0.f;
        #pragma unroll
        for (int t8 = 0; t8 < 8; ++t8) p += expf(lsm[(g * 8 + t8) * ESc + es] - m);
        ps[g * 16 + es] = p;
    }
    __syncthreads();
    if (tid < 16) {
        float s = 0.f;
        #pragma unroll
        for (int g = 0; g < 16; ++g) s += ps[g * 16 + tid];
        g_mch[((size_t)b * NCHUNK + chunk) * ESc + tid] = cm[tid];
        g_sch[((size_t)b * NCHUNK + chunk) * ESc + tid] = s;
    }

    // ---- Phase C: partial xs, thread = (12 d as 3 float4) x (4 es) ----
    {
        const int f4i = tid & 63;
        const int esq = tid >> 6;
        u64 acc2[4][3][2];
        #pragma unroll
        for (int e = 0; e < 4; ++e)
            #pragma unroll
            for (int j = 0; j < 3; ++j) { acc2[e][j][0] = 0ull; acc2[e][j][1] = 0ull; }

        const int dbase = f4i * 4;
        #pragma unroll 2
        for (int t = 0; t < TOK; ++t) {
            const float4 xv0 = __ldg((const float4*)(xc + (size_t)t * Dc + dbase));
            const float4 xv1 = __ldg((const float4*)(xc + (size_t)t * Dc + dbase + 256));
            const float4 xv2 = __ldg((const float4*)(xc + (size_t)t * Dc + dbase + 512));
            const u64 x0l = pk2(xv0.x, xv0.y), x0h = pk2(xv0.z, xv0.w);
            const u64 x1l = pk2(xv1.x, xv1.y), x1h = pk2(xv1.z, xv1.w);
            const u64 x2l = pk2(xv2.x, xv2.y), x2h = pk2(xv2.z, xv2.w);
            const float4 dv = *(const float4*)&dsm[t * ESc + esq * 4];
            const u64 w0 = dup2(dv.x), w1 = dup2(dv.y), w2 = dup2(dv.z), w3 = dup2(dv.w);
            fma2(acc2[0][0][0], w0, x0l); fma2(acc2[0][0][1], w0, x0h);
            fma2(acc2[0][1][0], w0, x1l); fma2(acc2[0][1][1], w0, x1h);
            fma2(acc2[0][2][0], w0, x2l); fma2(acc2[0][2][1], w0, x2h);
            fma2(acc2[1][0][0], w1, x0l); fma2(acc2[1][0][1], w1, x0h);
            fma2(acc2[1][1][0], w1, x1l); fma2(acc2[1][1][1], w1, x1h);
            fma2(acc2[1][2][0], w1, x2l); fma2(acc2[1][2][1], w1, x2h);
            fma2(acc2[2][0][0], w2, x0l); fma2(acc2[2][0][1], w2, x0h);
            fma2(acc2[2][1][0], w2, x1l); fma2(acc2[2][1][1], w2, x1h);
            fma2(acc2[2][2][0], w2, x2l); fma2(acc2[2][2][1], w2, x2h);
            fma2(acc2[3][0][0], w3, x0l); fma2(acc2[3][0][1], w3, x0h);
            fma2(acc2[3][1][0], w3, x1l); fma2(acc2[3][1][1], w3, x1h);
            fma2(acc2[3][2][0], w3, x2l); fma2(acc2[3][2][1], w3, x2h);
        }
        float* out = g_pxs + ((size_t)(b * NCHUNK + chunk) * ESc) * Dc;
        #pragma unroll
        for (int e = 0; e < 4; ++e) {
            const int es = esq * 4 + e;
            #pragma unroll
            for (int j = 0; j < 3; ++j) {
                float4 o;
                up2(acc2[e][j][0], o.x, o.y);
                up2(acc2[e][j][1], o.z, o.w);
                *(float4*)(out + (size_t)es * Dc + dbase + 256 * j) = o;
            }
        }
    }
}

// ================= K2: reduce xs partials + pack row pairs =================
__global__ void __launch_bounds__(256) k2_reduce_xs() {
    const int idx = blockIdx.x * 256 + threadIdx.x;
    const int b = idx / (ESc * Dc);
    const int rem = idx % (ESc * Dc);
    const int es = rem / Dc, d = rem % Dc;
    float s = 0.f;
    #pragma unroll 8
    for (int c = 0; c < NCHUNK; ++c)
        s += g_pxs[((size_t)(b * NCHUNK + c)) * (ESc * Dc) + rem];
    const int e = es >> 1, sl = es & 1, row = b * 2 + sl;
    ((float*)g_xs2)[((size_t)e * Dc + d) * 16 + row] = s;
}

// ================= K4: finalize colmax / inv colsum =================
__global__ void k4_finalize() {
    const int i = threadIdx.x;
    if (i >= Bc * ESc) return;
    const int b = i >> 4, es = i & 15;
    float M = -1e30f;
    #pragma unroll 8
    for (int c = 0; c < NCHUNK; ++c)
        M = fmaxf(M, g_mch[((size_t)b * NCHUNK + c) * ESc + es]);
    float S = 0.f;
    #pragma unroll 8
    for (int c = 0; c < NCHUNK; ++c) {
        const size_t o = ((size_t)b * NCHUNK + c) * ESc + es;
        S += expf(g_mch[o] - M) * g_sch[o];
    }
    g_cmaxf[i] = M;
    g_inv[i] = 1.f / S;
}

// ================= K5: FFN1 + GELU  (grid (96, 8), 256 thr) =================
// thread: fi=t&7 (4 f), rg=(t>>3)&7 (row-pair), ds=t>>6 (d quarter)
#define K5_SMEM_BYTES (Dc * 8 * 8 + 3 * 256 * 8)   // 49152 + 6144 = 55296
__global__ void __launch_bounds__(256, 4)
k5_ffn1(const float* __restrict__ w1, const float* __restrict__ b1) {
    extern __shared__ __align__(16) char k5smem[];
    u64* xsm = (u64*)k5smem;             // Dc*8
    u64* red = xsm + Dc * 8;             // 3*256
    const int e = blockIdx.y;
    const int fbase = blockIdx.x * 32;
    const int tid = threadIdx.x;
    for (int i = tid; i < Dc * 8; i += 256) xsm[i] = g_xs2[(size_t)e * Dc * 8 + i];
    __syncthreads();

    const int fi = tid & 7;
    const int rg = (tid >> 3) & 7;
    const int ds = tid >> 6;
    const int f = fbase + fi * 4;

    u64 a0 = 0, a1 = 0, a2 = 0, a3 = 0;
    const float* w = w1 + (size_t)e * Dc * Hc + f;
    const int dlo = ds * 192;
    #pragma unroll 8
    for (int d = dlo; d < dlo + 192; ++d) {
        const float4 wv = __ldg((const float4*)(w + (size_t)d * Hc));
        const u64 xs = xsm[d * 8 + rg];
        fma2(a0, dup2(wv.x), xs);
        fma2(a1, dup2(wv.y), xs);
        fma2(a2, dup2(wv.z), xs);
        fma2(a3, dup2(wv.w), xs);
    }
    const int ri = tid & 63;
    if (ds > 0) {
        u64* r = red + (ds - 1) * 256 + ri * 4;
        r[0] = a0; r[1] = a1; r[2] = a2; r[3] = a3;
    }
    __syncthreads();
    if (ds == 0) {
        #pragma unroll
        for (int q = 0; q < 3; ++q) {
            const u64* r = red + q * 256 + ri * 4;
            a0 = add2(a0, r[0]); a1 = add2(a1, r[1]);
            a2 = add2(a2, r[2]); a3 = add2(a3, r[3]);
        }
        const float4 bv = __ldg((const float4*)(b1 + (size_t)e * Hc + f));
        u64 accs[4] = {a0, a1, a2, a3};
        const float bvs[4] = {bv.x, bv.y, bv.z, bv.w};
        #pragma unroll
        for (int j = 0; j < 4; ++j) {
            float lo, hi; up2(accs[j], lo, hi);
            g_h2[((size_t)e * Hc + f + j) * 8 + rg] =
                pk2(gelu_exact(lo + bvs[j]), gelu_exact(hi + bvs[j]));
        }
    }
}

// ================= K6: FFN2 + bias  (grid (48, 8), 256 thr) =================
// thread: dq=t&3 (4 d), rh=(t>>2)&1 (4 row-pairs), fs=t>>3 (32 f-slices of 96)
__global__ void __launch_bounds__(256, 3)
k6_ffn2(const float* __restrict__ w2, const float* __restrict__ b2) {
    __shared__ __align__(16) u64 red[32 * 128];    // 32KB: [fs][(dq*4+j)*8 + rh*4+r]
    const int e = blockIdx.y;
    const int d0 = blockIdx.x * 16;
    const int tid = threadIdx.x;
    const int dq = tid & 3, rh = (tid >> 2) & 1, fs = tid >> 3;

    u64 acc[4][4];
    #pragma unroll
    for (int j = 0; j < 4; ++j)
        #pragma unroll
        for (int r = 0; r < 4; ++r) acc[j][r] = 0ull;

    const float* w = w2 + (size_t)e * Hc * Dc + d0 + dq * 4;
    const ulonglong2* h2 = (const ulonglong2*)(g_h2 + (size_t)e * Hc * 8);
    const int f0 = fs * 96;
    #pragma unroll 4
    for (int f = f0; f < f0 + 96; ++f) {
        const float4 wv = __ldg((const float4*)(w + (size_t)f * Dc));
        const ulonglong2 ha = h2[f * 4 + rh * 2];
        const ulonglong2 hb = h2[f * 4 + rh * 2 + 1];
        const u64 wd0 = dup2(wv.x), wd1 = dup2(wv.y), wd2 = dup2(wv.z), wd3 = dup2(wv.w);
        fma2(acc[0][0], wd0, ha.x); fma2(acc[0][1], wd0, ha.y);
        fma2(acc[0][2], wd0, hb.x); fma2(acc[0][3], wd0, hb.y);
        fma2(acc[1][0], wd1, ha.x); fma2(acc[1][1], wd1, ha.y);
        fma2(acc[1][2], wd1, hb.x); fma2(acc[1][3], wd1, hb.y);
        fma2(acc[2][0], wd2, ha.x); fma2(acc[2][1], wd2, ha.y);
        fma2(acc[2][2], wd2, hb.x); fma2(acc[2][3], wd2, hb.y);
        fma2(acc[3][0], wd3, ha.x); fma2(acc[3][1], wd3, ha.y);
        fma2(acc[3][2], wd3, hb.x); fma2(acc[3][3], wd3, hb.y);
    }
    #pragma unroll
    for (int j = 0; j < 4; ++j)
        #pragma unroll
        for (int r = 0; r < 4; ++r)
            red[fs * 128 + (dq * 4 + j) * 8 + rh * 4 + r] = acc[j][r];
    __syncthreads();
    if (tid < 128) {
        const int d_loc = tid >> 3, rp = tid & 7;
        u64 s = red[d_loc * 8 + rp];
        #pragma unroll 8
        for (int f2 = 1; f2 < 32; ++f2) s = add2(s, red[f2 * 128 + d_loc * 8 + rp]);
        float lo, hi; up2(s, lo, hi);
        const float bb2 = __ldg(b2 + (size_t)e * Dc + d0 + d_loc);
        const int r0 = 2 * rp, r1 = 2 * rp + 1;
        g_ys[((size_t)(r0 >> 1) * ESc + e * 2 + (r0 & 1)) * Dc + d0 + d_loc] = lo + bb2;
        g_ys[((size_t)(r1 >> 1) * ESc + e * 2 + (r1 & 1)) * Dc + d0 + d_loc] = hi + bb2;
    }
}

// ================= K7: combine softmax + y = c @ ys  (grid (64, 8), 64-token tiles) ==
#define K7_SMEM_FLOATS (ESc * Dc + ESc * TOK7 + 32)
extern "C" __global__ void __launch_bounds__(256)
k7_combine(float* __restrict__ y) {
    extern __shared__ float smemf[];
    float* ysm = smemf;                       // [16][768]
    float* csm = smemf + ESc * Dc;            // [16][64]
    float* cm  = smemf + ESc * Dc + ESc * TOK7;
    float* inv = cm + 16;

    const int b = blockIdx.y, chunk = blockIdx.x, tid = threadIdx.x;
    {
        const float4* src = (const float4*)(g_ys + (size_t)b * ESc * Dc);
        float4* dst = (float4*)ysm;
        #pragma unroll
        for (int k = 0; k < 12; ++k) dst[tid + k * 256] = src[tid + k * 256];
    }
    if (tid < 16) { cm[tid] = g_cmaxf[b * ESc + tid]; inv[tid] = g_inv[b * ESc + tid]; }
    __syncthreads();

    {   // combine weights: 1024 entries, 4 per thread (same es, consecutive t)
        const int i0 = tid * 4;
        const int es = i0 >> 6;
        const int t0 = i0 & 63;
        const float m = cm[es], iv = inv[es];
        const float* lp = g_logits + ((size_t)b * Nc + chunk * TOK7 + t0) * ESc + es;
        #pragma unroll
        for (int q = 0; q < 4; ++q)
            csm[es * TOK7 + t0 + q] = expf(lp[q * ESc] - m) * iv;
    }
    __syncthreads();

    const int dg = tid & 63, tg = tid >> 6;
    const int dbase = dg * 4;
    float* yb = y + ((size_t)b * Nc + chunk * TOK7) * Dc;
    for (int tq = 0; tq < 4; ++tq) {
        const int trel = tg * 16 + tq * 4;
        u64 acc[4][3][2];
        #pragma unroll
        for (int t = 0; t < 4; ++t)
            #pragma unroll
            for (int j = 0; j < 3; ++j) { acc[t][j][0] = 0ull; acc[t][j][1] = 0ull; }
        #pragma unroll
        for (int es = 0; es < 16; ++es) {
            float4 c4 = *(const float4*)&csm[es * TOK7 + trel];
            u64 cd0 = dup2(c4.x), cd1 = dup2(c4.y), cd2 = dup2(c4.z), cd3 = dup2(c4.w);
            #pragma unroll
            for (int j = 0; j < 3; ++j) {
                float4 yv = *(const float4*)&ysm[es * Dc + dbase + 256 * j];
                u64 ylo = pk2(yv.x, yv.y), yhi = pk2(yv.z, yv.w);
                fma2(acc[0][j][0], cd0, ylo); fma2(acc[0][j][1], cd0, yhi);
                fma2(acc[1][j][0], cd1, ylo); fma2(acc[1][j][1], cd1, yhi);
                fma2(acc[2][j][0], cd2, ylo); fma2(acc[2][j][1], cd2, yhi);
                fma2(acc[3][j][0], cd3, ylo); fma2(acc[3][j][1], cd3, yhi);
            }
        }
        #pragma unroll
        for (int t = 0; t < 4; ++t) {
            float* yr = yb + (size_t)(trel + t) * Dc;
            #pragma unroll
            for (int j = 0; j < 3; ++j) {
                float4 o;
                up2(acc[t][j][0], o.x, o.y);
                up2(acc[t][j][1], o.z, o.w);
                *(float4*)(yr + dbase + 256 * j) = o;
            }
        }
    }
}

// ================= host =================
extern "C" void kernel_launch(void* const* d_in, const int* in_sizes, int n_in,
                              void* d_out, int out_size) {
    const float* x   = (const float*)d_in[0];
    const float* phi = (const float*)d_in[1];
    const float* w1  = (const float*)d_in[2];
    const float* b1  = (const float*)d_in[3];
    const float* w2  = (const float*)d_in[4];
    const float* b2  = (const float*)d_in[5];
    float* y = (float*)d_out;

    cudaFuncSetAttribute(k1_fused, cudaFuncAttributeMaxDynamicSharedMemorySize,
                         K1_SMEM_FLOATS * sizeof(float));
    cudaFuncSetAttribute(k5_ffn1, cudaFuncAttributeMaxDynamicSharedMemorySize,
                         K5_SMEM_BYTES);
    cudaFuncSetAttribute(k7_combine, cudaFuncAttributeMaxDynamicSharedMemorySize,
                         K7_SMEM_FLOATS * sizeof(float));
    (void)in_sizes; (void)n_in; (void)out_size;

    k1_fused<<<dim3(NCHUNK, Bc), 256, K1_SMEM_FLOATS * sizeof(float)>>>(x, phi);
    k2_reduce_xs<<<(Bc * ESc * Dc) / 256, 256>>>();
    k4_finalize<<<1, 128>>>();
    k5_ffn1<<<dim3(Hc / 32, Ec), 256, K5_SMEM_BYTES>>>(w1, b1);
    k6_ffn2<<<dim3(Dc / 16, Ec), 256>>>(w2, b2);
    k7_combine<<<dim3(Nc / TOK7, Bc), 256, K7_SMEM_FLOATS * sizeof(float)>>>(y);
}

// round 6
// speedup vs baseline: 3.3627x; 1.2179x over previous
#include <cuda_runtime.h>
#include <math.h>

#define Bc 8
#define Nc 4096
#define Dc 768
#define Ec 8
#define ESc 16
#define Hc 3072
#define NCH1 64
#define TOK1 64
#define TOK7 64

typedef unsigned long long u64;
typedef unsigned int u32;

// ----------------- scratch -----------------
__device__ float g_logits[Bc * Nc * ESc];
__device__ float g_pxs[Bc * NCH1 * ESc * Dc];          // 25.2 MB
__device__ __align__(16) u64 g_xs2[Ec * Dc * 8];       // [e][d][rp]
__device__ float g_mch[Bc * NCH1 * ESc];
__device__ float g_sch[Bc * NCH1 * ESc];
__device__ float g_cmaxf[Bc * ESc];
__device__ float g_inv[Bc * ESc];
__device__ __align__(16) u64 g_h2[Ec * Hc * 8];        // [e][f][rp]
__device__ float g_ys[Bc * ESc * Dc];

// ----------------- f32x2 helpers -----------------
__device__ __forceinline__ u64 pk2(float x, float y) {
    u64 r; asm("mov.b64 %0, {%1, %2};" : "=l"(r) : "f"(x), "f"(y)); return r;
}
__device__ __forceinline__ u64 dup2(float x) {
    u64 r; asm("mov.b64 %0, {%1, %1};" : "=l"(r) : "f"(x)); return r;
}
__device__ __forceinline__ void up2(u64 v, float& x, float& y) {
    asm("mov.b64 {%0, %1}, %2;" : "=f"(x), "=f"(y) : "l"(v));
}
__device__ __forceinline__ void fma2(u64& d, u64 a, u64 b) {
    asm("fma.rn.f32x2 %0, %1, %2, %0;" : "+l"(d) : "l"(a), "l"(b));
}
__device__ __forceinline__ u64 add2(u64 a, u64 b) {
    u64 r; asm("add.rn.f32x2 %0, %1, %2;" : "=l"(r) : "l"(a), "l"(b)); return r;
}
__device__ __forceinline__ float gelu_exact(float v) {
    return 0.5f * v * (1.0f + erff(v * 0.70710678118654752f));
}

// ---- k1 smem float offsets ----
#define OFF_PHI  0                      // 12288 floats (u64[768*8])
#define OFF_XT   12288                  // 64 x 65 = 4160
#define OFF_RED  16448                  // 1536 u64 = 3072 floats
#define OFF_LSM  19520                  // 64 x 16
#define OFF_DSM  20544                  // 64 x 16
#define OFF_GM   21568                  // 16 x 16
#define OFF_PS   21824                  // 16 x 16
#define OFF_CM   22080                  // 16
#define K1_SMEM_FLOATS 22096            // 88384 B

// ================= K1: fused logits + dispatch softmax + chunk colstats + partial xs ===
// grid (64, 8), 256 thr
extern "C" __global__ void __launch_bounds__(256)
k1_fused(const float* __restrict__ x, const float* __restrict__ phi) {
    extern __shared__ float smemf[];
    u64*   phiD = (u64*)(smemf + OFF_PHI);
    float* xT   = smemf + OFF_XT;
    u64*   red  = (u64*)(smemf + OFF_RED);
    float* lsm  = smemf + OFF_LSM;
    float* dsm  = smemf + OFF_DSM;
    float* gm   = smemf + OFF_GM;
    float* ps   = smemf + OFF_PS;
    float* cm   = smemf + OFF_CM;

    const int b = blockIdx.y, chunk = blockIdx.x;
    const int tid = threadIdx.x;
    const float* xc = x + ((size_t)b * Nc + chunk * TOK1) * Dc;

    {   // phi [768][16] -> u64 pairs, straight copy
        const u64* ph = (const u64*)phi;
        for (int i = tid; i < Dc * 8; i += 256) phiD[i] = ph[i];
    }

    // ---- Phase A: logits. thread = (tok 0..63, seg 0..3); seg covers 16 d per dblock --
    const int tok = tid & 63;
    const int seg = tid >> 6;
    u64 acc[8];
    #pragma unroll
    for (int j = 0; j < 8; ++j) acc[j] = 0ull;

    for (int db = 0; db < 12; ++db) {
        const int d0 = db * 64;
        __syncthreads();
        // stage x[64 tok][64 d] transposed via float4 loads
        #pragma unroll
        for (int k = 0; k < 4; ++k) {
            const int idx = tid + k * 256;          // 0..1023
            const int t = idx >> 4, dd4 = idx & 15;
            const float4 v = __ldg((const float4*)(xc + (size_t)t * Dc + d0 + dd4 * 4));
            xT[(dd4 * 4 + 0) * 65 + t] = v.x;
            xT[(dd4 * 4 + 1) * 65 + t] = v.y;
            xT[(dd4 * 4 + 2) * 65 + t] = v.z;
            xT[(dd4 * 4 + 3) * 65 + t] = v.w;
        }
        __syncthreads();
        const ulonglong2* pp = (const ulonglong2*)phiD;
        #pragma unroll 4
        for (int i = 0; i < 16; ++i) {
            const int dd = seg * 16 + i;
            const int d = d0 + dd;
            const u64 xd = dup2(xT[dd * 65 + tok]);
            ulonglong2 q0 = pp[d * 4 + 0];
            ulonglong2 q1 = pp[d * 4 + 1];
            ulonglong2 q2 = pp[d * 4 + 2];
            ulonglong2 q3 = pp[d * 4 + 3];
            fma2(acc[0], xd, q0.x); fma2(acc[1], xd, q0.y);
            fma2(acc[2], xd, q1.x); fma2(acc[3], xd, q1.y);
            fma2(acc[4], xd, q2.x); fma2(acc[5], xd, q2.y);
            fma2(acc[6], xd, q3.x); fma2(acc[7], xd, q3.y);
        }
    }
    __syncthreads();
    if (seg > 0) {
        u64* r = red + ((seg - 1) * 64 + tok) * 8;
        #pragma unroll
        for (int j = 0; j < 8; ++j) r[j] = acc[j];
    }
    __syncthreads();
    if (seg == 0) {
        #pragma unroll
        for (int q = 0; q < 3; ++q) {
            const u64* r = red + (q * 64 + tok) * 8;
            #pragma unroll
            for (int j = 0; j < 8; ++j) acc[j] = add2(acc[j], r[j]);
        }
        float l[16];
        #pragma unroll
        for (int j = 0; j < 8; ++j) up2(acc[j], l[2 * j], l[2 * j + 1]);
        float m = l[0];
        #pragma unroll
        for (int es = 1; es < 16; ++es) m = fmaxf(m, l[es]);
        float s = 0.f;
        float p[16];
        #pragma unroll
        for (int es = 0; es < 16; ++es) { p[es] = __expf(l[es] - m); s += p[es]; }
        const float inv = 1.f / s;
        u64* dl = (u64*)dsm;
        u64* ll = (u64*)lsm;
        #pragma unroll
        for (int j = 0; j < 8; ++j) {
            dl[tok * 8 + j] = pk2(p[2 * j] * inv, p[2 * j + 1] * inv);
            ll[tok * 8 + j] = pk2(l[2 * j], l[2 * j + 1]);
        }
    }
    __syncthreads();

    {   // raw logits -> global
        const size_t lbase = ((size_t)b * Nc + chunk * TOK1) * ESc;
        #pragma unroll
        for (int k = 0; k < 4; ++k) g_logits[lbase + tid + k * 256] = lsm[tid + k * 256];
    }

    // ---- Phase B: per-chunk column stats (16 groups x 4 tokens) ----
    {
        const int g = tid >> 4, es = tid & 15;
        float m = -1e30f;
        #pragma unroll
        for (int t4 = 0; t4 < 4; ++t4) m = fmaxf(m, lsm[(g * 4 + t4) * ESc + es]);
        gm[g * 16 + es] = m;
    }
    __syncthreads();
    if (tid < 16) {
        float m = gm[tid];
        #pragma unroll
        for (int g = 1; g < 16; ++g) m = fmaxf(m, gm[g * 16 + tid]);
        cm[tid] = m;
    }
    __syncthreads();
    {
        const int g = tid >> 4, es = tid & 15;
        const float m = cm[es];
        float p = 0.f;
        #pragma unroll
        for (int t4 = 0; t4 < 4; ++t4) p += __expf(lsm[(g * 4 + t4) * ESc + es] - m);
        ps[g * 16 + es] = p;
    }
    __syncthreads();
    if (tid < 16) {
        float s = 0.f;
        #pragma unroll
        for (int g = 0; g < 16; ++g) s += ps[g * 16 + tid];
        g_mch[((size_t)b * NCH1 + chunk) * ESc + tid] = cm[tid];
        g_sch[((size_t)b * NCH1 + chunk) * ESc + tid] = s;
    }

    // ---- Phase C: partial xs, thread = (12 d as 3 float4) x (4 es) ----
    {
        const int f4i = tid & 63;
        const int esq = tid >> 6;
        u64 acc2[4][3][2];
        #pragma unroll
        for (int e = 0; e < 4; ++e)
            #pragma unroll
            for (int j = 0; j < 3; ++j) { acc2[e][j][0] = 0ull; acc2[e][j][1] = 0ull; }

        const int dbase = f4i * 4;
        #pragma unroll 2
        for (int t = 0; t < TOK1; ++t) {
            const float4 xv0 = __ldg((const float4*)(xc + (size_t)t * Dc + dbase));
            const float4 xv1 = __ldg((const float4*)(xc + (size_t)t * Dc + dbase + 256));
            const float4 xv2 = __ldg((const float4*)(xc + (size_t)t * Dc + dbase + 512));
            const u64 x0l = pk2(xv0.x, xv0.y), x0h = pk2(xv0.z, xv0.w);
            const u64 x1l = pk2(xv1.x, xv1.y), x1h = pk2(xv1.z, xv1.w);
            const u64 x2l = pk2(xv2.x, xv2.y), x2h = pk2(xv2.z, xv2.w);
            const float4 dv = *(const float4*)&dsm[t * ESc + esq * 4];
            const u64 w0 = dup2(dv.x), w1 = dup2(dv.y), w2 = dup2(dv.z), w3 = dup2(dv.w);
            fma2(acc2[0][0][0], w0, x0l); fma2(acc2[0][0][1], w0, x0h);
            fma2(acc2[0][1][0], w0, x1l); fma2(acc2[0][1][1], w0, x1h);
            fma2(acc2[0][2][0], w0, x2l); fma2(acc2[0][2][1], w0, x2h);
            fma2(acc2[1][0][0], w1, x0l); fma2(acc2[1][0][1], w1, x0h);
            fma2(acc2[1][1][0], w1, x1l); fma2(acc2[1][1][1], w1, x1h);
            fma2(acc2[1][2][0], w1, x2l); fma2(acc2[1][2][1], w1, x2h);
            fma2(acc2[2][0][0], w2, x0l); fma2(acc2[2][0][1], w2, x0h);
            fma2(acc2[2][1][0], w2, x1l); fma2(acc2[2][1][1], w2, x1h);
            fma2(acc2[2][2][0], w2, x2l); fma2(acc2[2][2][1], w2, x2h);
            fma2(acc2[3][0][0], w3, x0l); fma2(acc2[3][0][1], w3, x0h);
            fma2(acc2[3][1][0], w3, x1l); fma2(acc2[3][1][1], w3, x1h);
            fma2(acc2[3][2][0], w3, x2l); fma2(acc2[3][2][1], w3, x2h);
        }
        float* out = g_pxs + ((size_t)(b * NCH1 + chunk) * ESc) * Dc;
        #pragma unroll
        for (int e = 0; e < 4; ++e) {
            const int es = esq * 4 + e;
            #pragma unroll
            for (int j = 0; j < 3; ++j) {
                float4 o;
                up2(acc2[e][j][0], o.x, o.y);
                up2(acc2[e][j][1], o.z, o.w);
                *(float4*)(out + (size_t)es * Dc + dbase + 256 * j) = o;
            }
        }
    }
}

// ================= K2: reduce xs partials + pack row pairs =================
__global__ void __launch_bounds__(256) k2_reduce_xs() {
    const int idx = blockIdx.x * 256 + threadIdx.x;
    const int b = idx / (ESc * Dc);
    const int rem = idx % (ESc * Dc);
    const int es = rem / Dc, d = rem % Dc;
    float s = 0.f;
    #pragma unroll 8
    for (int c = 0; c < NCH1; ++c)
        s += g_pxs[((size_t)(b * NCH1 + c)) * (ESc * Dc) + rem];
    const int e = es >> 1, sl = es & 1, row = b * 2 + sl;
    ((float*)g_xs2)[((size_t)e * Dc + d) * 16 + row] = s;
}

// ================= K4: finalize colmax / inv colsum =================
__global__ void k4_finalize() {
    const int i = threadIdx.x;
    if (i >= Bc * ESc) return;
    const int b = i >> 4, es = i & 15;
    float M = -1e30f;
    #pragma unroll 8
    for (int c = 0; c < NCH1; ++c)
        M = fmaxf(M, g_mch[((size_t)b * NCH1 + c) * ESc + es]);
    float S = 0.f;
    #pragma unroll 8
    for (int c = 0; c < NCH1; ++c) {
        const size_t o = ((size_t)b * NCH1 + c) * ESc + es;
        S += __expf(g_mch[o] - M) * g_sch[o];
    }
    g_cmaxf[i] = M;
    g_inv[i] = 1.f / S;
}

// ================= K5: FFN1 + GELU  (grid (48, 8), 256 thr) =================
// thread: fi=t&15 (4 f), rh=(t>>4)&1 (4 row-pairs), ds=t>>5 (8 segs of 96 d)
#define K5_SMEM_BYTES (Dc * 8 * 8 + 2048 * 8)   // 49152 + 16384 = 65536
__global__ void __launch_bounds__(256, 3)
k5_ffn1(const float* __restrict__ w1, const float* __restrict__ b1) {
    extern __shared__ __align__(16) char k5smem[];
    u64* xsm = (u64*)k5smem;             // Dc*8
    u64* red = xsm + Dc * 8;             // 2048
    const int e = blockIdx.y;
    const int fbase = blockIdx.x * 64;
    const int tid = threadIdx.x;
    {
        const ulonglong2* src = (const ulonglong2*)(g_xs2 + (size_t)e * Dc * 8);
        ulonglong2* dst = (ulonglong2*)xsm;
        #pragma unroll
        for (int k = 0; k < 12; ++k) dst[tid + k * 256] = src[tid + k * 256];
    }
    __syncthreads();

    const int fi = tid & 15;
    const int rh = (tid >> 4) & 1;
    const int ds = tid >> 5;
    const int lid32 = tid & 31;
    const int f = fbase + fi * 4;

    u64 acc[4][4];
    #pragma unroll
    for (int j = 0; j < 4; ++j)
        #pragma unroll
        for (int r = 0; r < 4; ++r) acc[j][r] = 0ull;

    const float* w = w1 + (size_t)e * Dc * Hc + f;
    const ulonglong2* x2 = (const ulonglong2*)xsm;
    const int dlo = ds * 96;
    #pragma unroll 4
    for (int d = dlo; d < dlo + 96; ++d) {
        const float4 wv = __ldg((const float4*)(w + (size_t)d * Hc));
        const ulonglong2 xa = x2[d * 4 + rh * 2];
        const ulonglong2 xb = x2[d * 4 + rh * 2 + 1];
        const u64 w0 = dup2(wv.x), w1d = dup2(wv.y), w2 = dup2(wv.z), w3 = dup2(wv.w);
        fma2(acc[0][0], w0, xa.x); fma2(acc[0][1], w0, xa.y);
        fma2(acc[0][2], w0, xb.x); fma2(acc[0][3], w0, xb.y);
        fma2(acc[1][0], w1d, xa.x); fma2(acc[1][1], w1d, xa.y);
        fma2(acc[1][2], w1d, xb.x); fma2(acc[1][3], w1d, xb.y);
        fma2(acc[2][0], w2, xa.x); fma2(acc[2][1], w2, xa.y);
        fma2(acc[2][2], w2, xb.x); fma2(acc[2][3], w2, xb.y);
        fma2(acc[3][0], w3, xa.x); fma2(acc[3][1], w3, xa.y);
        fma2(acc[3][2], w3, xb.x); fma2(acc[3][3], w3, xb.y);
    }

    // tree reduce over 8 d-segs
    if (ds >= 4) {
        u64* r = red + ((ds - 4) * 32 + lid32) * 16;
        #pragma unroll
        for (int j = 0; j < 4; ++j)
            #pragma unroll
            for (int k = 0; k < 4; ++k) r[j * 4 + k] = acc[j][k];
    }
    __syncthreads();
    if (ds < 4) {
        const u64* r = red + (ds * 32 + lid32) * 16;
        #pragma unroll
        for (int j = 0; j < 4; ++j)
            #pragma unroll
            for (int k = 0; k < 4; ++k) acc[j][k] = add2(acc[j][k], r[j * 4 + k]);
    }
    __syncthreads();
    if (ds >= 2 && ds < 4) {
        u64* r = red + ((ds - 2) * 32 + lid32) * 16;
        #pragma unroll
        for (int j = 0; j < 4; ++j)
            #pragma unroll
            for (int k = 0; k < 4; ++k) r[j * 4 + k] = acc[j][k];
    }
    __syncthreads();
    if (ds < 2) {
        const u64* r = red + (ds * 32 + lid32) * 16;
        #pragma unroll
        for (int j = 0; j < 4; ++j)
            #pragma unroll
            for (int k = 0; k < 4; ++k) acc[j][k] = add2(acc[j][k], r[j * 4 + k]);
    }
    __syncthreads();
    if (ds == 1) {
        u64* r = red + lid32 * 16;
        #pragma unroll
        for (int j = 0; j < 4; ++j)
            #pragma unroll
            for (int k = 0; k < 4; ++k) r[j * 4 + k] = acc[j][k];
    }
    __syncthreads();
    if (ds == 0) {
        u64* r = red + lid32 * 16;
        #pragma unroll
        for (int j = 0; j < 4; ++j)
            #pragma unroll
            for (int k = 0; k < 4; ++k) r[j * 4 + k] = add2(acc[j][k], r[j * 4 + k]);
    }
    __syncthreads();
    // distributed GELU epilogue: 512 u64, 2 per thread
    #pragma unroll
    for (int q = 0; q < 2; ++q) {
        const int flat = tid * 2 + q;
        const int t32 = flat >> 4, j = flat & 15;
        const int fi2 = t32 & 15, rh2 = t32 >> 4;
        const int jf = j >> 2, jr = j & 3;
        const int f2 = fbase + fi2 * 4 + jf;
        const int rp = rh2 * 4 + jr;
        const float bv = __ldg(b1 + (size_t)e * Hc + f2);
        float lo, hi; up2(red[flat], lo, hi);
        g_h2[((size_t)e * Hc + f2) * 8 + rp] =
            pk2(gelu_exact(lo + bv), gelu_exact(hi + bv));
    }
}

// ================= K6: FFN2 + bias  (grid (48, 8), 256 thr) =================
__global__ void __launch_bounds__(256, 3)
k6_ffn2(const float* __restrict__ w2, const float* __restrict__ b2) {
    __shared__ __align__(16) u64 red[32 * 128];    // 32KB
    const int e = blockIdx.y;
    const int d0 = blockIdx.x * 16;
    const int tid = threadIdx.x;
    const int dq = tid & 3, rh = (tid >> 2) & 1, fs = tid >> 3;

    u64 acc[4][4];
    #pragma unroll
    for (int j = 0; j < 4; ++j)
        #pragma unroll
        for (int r = 0; r < 4; ++r) acc[j][r] = 0ull;

    const float* w = w2 + (size_t)e * Hc * Dc + d0 + dq * 4;
    const ulonglong2* h2 = (const ulonglong2*)(g_h2 + (size_t)e * Hc * 8);
    const int f0 = fs * 96;
    #pragma unroll 4
    for (int f = f0; f < f0 + 96; ++f) {
        const float4 wv = __ldg((const float4*)(w + (size_t)f * Dc));
        const ulonglong2 ha = h2[f * 4 + rh * 2];
        const ulonglong2 hb = h2[f * 4 + rh * 2 + 1];
        const u64 wd0 = dup2(wv.x), wd1 = dup2(wv.y), wd2 = dup2(wv.z), wd3 = dup2(wv.w);
        fma2(acc[0][0], wd0, ha.x); fma2(acc[0][1], wd0, ha.y);
        fma2(acc[0][2], wd0, hb.x); fma2(acc[0][3], wd0, hb.y);
        fma2(acc[1][0], wd1, ha.x); fma2(acc[1][1], wd1, ha.y);
        fma2(acc[1][2], wd1, hb.x); fma2(acc[1][3], wd1, hb.y);
        fma2(acc[2][0], wd2, ha.x); fma2(acc[2][1], wd2, ha.y);
        fma2(acc[2][2], wd2, hb.x); fma2(acc[2][3], wd2, hb.y);
        fma2(acc[3][0], wd3, ha.x); fma2(acc[3][1], wd3, ha.y);
        fma2(acc[3][2], wd3, hb.x); fma2(acc[3][3], wd3, hb.y);
    }
    #pragma unroll
    for (int j = 0; j < 4; ++j)
        #pragma unroll
        for (int r = 0; r < 4; ++r)
            red[fs * 128 + (dq * 4 + j) * 8 + rh * 4 + r] = acc[j][r];
    __syncthreads();
    if (tid < 128) {
        const int d_loc = tid >> 3, rp = tid & 7;
        u64 s = red[d_loc * 8 + rp];
        #pragma unroll 8
        for (int f2 = 1; f2 < 32; ++f2) s = add2(s, red[f2 * 128 + d_loc * 8 + rp]);
        float lo, hi; up2(s, lo, hi);
        const float bb2 = __ldg(b2 + (size_t)e * Dc + d0 + d_loc);
        const int r0 = 2 * rp, r1 = 2 * rp + 1;
        g_ys[((size_t)(r0 >> 1) * ESc + e * 2 + (r0 & 1)) * Dc + d0 + d_loc] = lo + bb2;
        g_ys[((size_t)(r1 >> 1) * ESc + e * 2 + (r1 & 1)) * Dc + d0 + d_loc] = hi + bb2;
    }
}

// ================= K7: combine softmax + y = c @ ys  (grid (64, 8)) =================
#define K7_SMEM_FLOATS (ESc * Dc + ESc * TOK7 + 32)
extern "C" __global__ void __launch_bounds__(256)
k7_combine(float* __restrict__ y) {
    extern __shared__ float smemf[];
    float* ysm = smemf;                       // [16][768]
    float* csm = smemf + ESc * Dc;            // [16][64]
    float* cm  = smemf + ESc * Dc + ESc * TOK7;
    float* inv = cm + 16;

    const int b = blockIdx.y, chunk = blockIdx.x, tid = threadIdx.x;
    {
        const float4* src = (const float4*)(g_ys + (size_t)b * ESc * Dc);
        float4* dst = (float4*)ysm;
        #pragma unroll
        for (int k = 0; k < 12; ++k) dst[tid + k * 256] = src[tid + k * 256];
    }
    if (tid < 16) { cm[tid] = g_cmaxf[b * ESc + tid]; inv[tid] = g_inv[b * ESc + tid]; }
    __syncthreads();

    {   // combine weights: 1024 entries, 4 per thread
        const int i0 = tid * 4;
        const int es = i0 >> 6;
        const int t0 = i0 & 63;
        const float m = cm[es], iv = inv[es];
        const float* lp = g_logits + ((size_t)b * Nc + chunk * TOK7 + t0) * ESc + es;
        #pragma unroll
        for (int q = 0; q < 4; ++q)
            csm[es * TOK7 + t0 + q] = __expf(lp[q * ESc] - m) * iv;
    }
    __syncthreads();

    const int dg = tid & 63, tg = tid >> 6;
    const int dbase = dg * 4;
    float* yb = y + ((size_t)b * Nc + chunk * TOK7) * Dc;
    for (int tq = 0; tq < 4; ++tq) {
        const int trel = tg * 16 + tq * 4;
        u64 acc[4][3][2];
        #pragma unroll
        for (int t = 0; t < 4; ++t)
            #pragma unroll
            for (int j = 0; j < 3; ++j) { acc[t][j][0] = 0ull; acc[t][j][1] = 0ull; }
        #pragma unroll
        for (int es = 0; es < 16; ++es) {
            float4 c4 = *(const float4*)&csm[es * TOK7 + trel];
            u64 cd0 = dup2(c4.x), cd1 = dup2(c4.y), cd2 = dup2(c4.z), cd3 = dup2(c4.w);
            #pragma unroll
            for (int j = 0; j < 3; ++j) {
                float4 yv = *(const float4*)&ysm[es * Dc + dbase + 256 * j];
                u64 ylo = pk2(yv.x, yv.y), yhi = pk2(yv.z, yv.w);
                fma2(acc[0][j][0], cd0, ylo); fma2(acc[0][j][1], cd0, yhi);
                fma2(acc[1][j][0], cd1, ylo); fma2(acc[1][j][1], cd1, yhi);
                fma2(acc[2][j][0], cd2, ylo); fma2(acc[2][j][1], cd2, yhi);
                fma2(acc[3][j][0], cd3, ylo); fma2(acc[3][j][1], cd3, yhi);
            }
        }
        #pragma unroll
        for (int t = 0; t < 4; ++t) {
            float* yr = yb + (size_t)(trel + t) * Dc;
            #pragma unroll
            for (int j = 0; j < 3; ++j) {
                float4 o;
                up2(acc[t][j][0], o.x, o.y);
                up2(acc[t][j][1], o.z, o.w);
                *(float4*)(yr + dbase + 256 * j) = o;
            }
        }
    }
}

// ================= host =================
extern "C" void kernel_launch(void* const* d_in, const int* in_sizes, int n_in,
                              void* d_out, int out_size) {
    const float* x   = (const float*)d_in[0];
    const float* phi = (const float*)d_in[1];
    const float* w1  = (const float*)d_in[2];
    const float* b1  = (const float*)d_in[3];
    const float* w2  = (const float*)d_in[4];
    const float* b2  = (const float*)d_in[5];
    float* y = (float*)d_out;

    cudaFuncSetAttribute(k1_fused, cudaFuncAttributeMaxDynamicSharedMemorySize,
                         K1_SMEM_FLOATS * sizeof(float));
    cudaFuncSetAttribute(k5_ffn1, cudaFuncAttributeMaxDynamicSharedMemorySize,
                         K5_SMEM_BYTES);
    cudaFuncSetAttribute(k7_combine, cudaFuncAttributeMaxDynamicSharedMemorySize,
                         K7_SMEM_FLOATS * sizeof(float));
    (void)in_sizes; (void)n_in; (void)out_size;

    k1_fused<<<dim3(NCH1, Bc), 256, K1_SMEM_FLOATS * sizeof(float)>>>(x, phi);
    k2_reduce_xs<<<(Bc * ESc * Dc) / 256, 256>>>();
    k4_finalize<<<1, 128>>>();
    k5_ffn1<<<dim3(Hc / 64, Ec), 256, K5_SMEM_BYTES>>>(w1, b1);
    k6_ffn2<<<dim3(Dc / 16, Ec), 256>>>(w2, b2);
    k7_combine<<<dim3(Nc / TOK7, Bc), 256, K7_SMEM_FLOATS * sizeof(float)>>>(y);
}